// round 7
// baseline (speedup 1.0000x reference)
#include <cuda_runtime.h>
#include <cuda_fp16.h>
#include <cstdint>

#define D 128
#define MAXN 100096
#define EMAX 1700000
#define SPU 132
#define GEMM_SMEM (96 * 132 * 8)   // 101376 bytes, both GEMM kernels

__device__ __half g_hs [MAXN * D];    // fp16: dis[i] * (x W^T + b)
__device__ __half g_buf[MAXN * D];    // fp16 layer output -> next layer input
__device__ uint2  g_wsp[3][64 * 128]; // pre-split W: {hi2, lo2} per (k2, col)
__device__ int    g_deg[MAXN];
__device__ int    g_indeg[MAXN];
__device__ int    g_off[MAXN + 1];
__device__ int    g_pos[MAXN];
__device__ int    g_csr[EMAX];
__device__ float  g_dis[MAXN];
__device__ int    g_is64;

__device__ __forceinline__ uint32_t packh2(float a, float b) {
    __half2 h = __floats2half2_rn(a, b);
    return *reinterpret_cast<uint32_t*>(&h);
}

// --------------------------------------------------------------------------
// preamble 1: dtype detect + init deg/indeg + W pre-split (all 3 layers)
// --------------------------------------------------------------------------
__global__ void k_pre(const int* __restrict__ e32, int n,
                      const float* __restrict__ W1,
                      const float* __restrict__ W2,
                      const float* __restrict__ W3) {
    int i = blockIdx.x * blockDim.x + threadIdx.x;
    if (i == 0) {
        int nz = 0;
        #pragma unroll 1
        for (int q = 0; q < 64; q++) nz += (e32[2 * q + 1] != 0);
        g_is64 = (nz == 0) ? 1 : 0;
    }
    if (i < n) { g_deg[i] = 1; g_indeg[i] = 0; }
    if (i < 3 * 8192) {
        const int l   = i >> 13;
        const int rem = i & 8191;
        const int k2  = rem >> 7;
        const int col = rem & 127;
        const float* W = (l == 0) ? W1 : (l == 1) ? W2 : W3;
        float w0 = W[col * 128 + 2 * k2];
        float w1 = W[col * 128 + 2 * k2 + 1];
        float h0f = __half2float(__float2half_rn(w0));
        float h1f = __half2float(__float2half_rn(w1));
        g_wsp[l][k2 * 128 + col] =
            make_uint2(packh2(w0, w1), packh2(w0 - h0f, w1 - h1f));
    }
}

__global__ void k_count(const void* __restrict__ ep, long long E) {
    long long e = (long long)blockIdx.x * blockDim.x + threadIdx.x;
    if (e >= E) return;
    int r, c;
    if (g_is64) {
        const long long* p = (const long long*)ep;
        r = (int)p[e]; c = (int)p[e + E];
    } else {
        const int* p = (const int*)ep;
        r = p[e]; c = p[e + E];
    }
    atomicAdd(&g_deg[r], 1);
    atomicAdd(&g_indeg[c], 1);
}

__global__ __launch_bounds__(1024) void k_scan_dis(int n) {
    __shared__ int s[1024];
    const int t = threadIdx.x;
    const int chunk = (n + 1023) / 1024;
    const int start = t * chunk;
    const int end = min(start + chunk, n);
    int sum = 0;
    for (int i = start; i < end; i++) {
        sum += g_indeg[i];
        g_dis[i] = rsqrtf((float)g_deg[i]);
    }
    s[t] = sum;
    __syncthreads();
    for (int o = 1; o < 1024; o <<= 1) {
        int v = (t >= o) ? s[t - o] : 0;
        __syncthreads();
        s[t] += v;
        __syncthreads();
    }
    int run = (t == 0) ? 0 : s[t - 1];
    for (int i = start; i < end; i++) {
        g_off[i] = run;
        g_pos[i] = run;
        run += g_indeg[i];
    }
    if (t == 1023) g_off[n] = s[1023];
}

__global__ void k_fill(const void* __restrict__ ep, long long E) {
    long long e = (long long)blockIdx.x * blockDim.x + threadIdx.x;
    if (e >= E) return;
    int r, c;
    if (g_is64) {
        const long long* p = (const long long*)ep;
        r = (int)p[e]; c = (int)p[e + E];
    } else {
        const int* p = (const int*)ep;
        r = p[e]; c = p[e + E];
    }
    int p = atomicAdd(&g_pos[c], 1);
    g_csr[p] = r;
}

// --------------------------------------------------------------------------
// fp16 m16n8k16 MMA (fp32 accumulate)
// --------------------------------------------------------------------------
__device__ __forceinline__ void mma_f16(float c[4],
                                        uint32_t a0, uint32_t a1, uint32_t a2, uint32_t a3,
                                        uint32_t b0, uint32_t b1) {
    asm volatile(
        "mma.sync.aligned.m16n8k16.row.col.f32.f16.f16.f32 "
        "{%0,%1,%2,%3}, {%4,%5,%6,%7}, {%8,%9}, {%0,%1,%2,%3};"
        : "+f"(c[0]), "+f"(c[1]), "+f"(c[2]), "+f"(c[3])
        : "r"(a0), "r"(a1), "r"(a2), "r"(a3), "r"(b0), "r"(b1));
}

// layer-1 GEMM: fp32 X, X and W split into fp16 hi/lo (3 MMAs / product).
// Whole W-split tile resident in smem; X loaded in 2 k-halves.
__global__ __launch_bounds__(256) void k_gemm1(const float* __restrict__ X,
                                               const uint2* __restrict__ Wsp,
                                               const float* __restrict__ Bv,
                                               int n) {
    extern __shared__ char smem[];
    uint2* sB = (uint2*)smem;                 // [64][SPU] {whi2, wlo2}
    uint2* sA = sB + 64 * SPU;                // [32][SPU] {xhi2, xlo2} (one k-half)

    const int tid  = threadIdx.x;
    const int lane = tid & 31;
    const int wid  = tid >> 5;
    const int warpRow = wid >> 1;
    const int warpCol = wid & 1;
    const int row0 = blockIdx.x * 128;
    const int lr = lane >> 2;
    const int lq = lane & 3;

    // load full pre-split W
    #pragma unroll
    for (int it = 0; it < 32; it++) {
        int j = it * 256 + tid;
        int kk2 = j >> 7;
        int col = j & 127;
        sB[kk2 * SPU + col] = Wsp[j];
    }

    float c[2][8][4];
    #pragma unroll
    for (int mt = 0; mt < 2; mt++)
        #pragma unroll
        for (int nt = 0; nt < 8; nt++)
            #pragma unroll
            for (int q = 0; q < 4; q++) c[mt][nt][q] = 0.f;

    #pragma unroll
    for (int h = 0; h < 2; h++) {
        // load + split X for k in [64h, 64h+64)
        #pragma unroll
        for (int it = 0; it < 8; it++) {
            int idx = it * 256 + tid;          // 0..2047
            int r = idx >> 4;                  // 0..127
            int kq = (idx & 15) * 4;           // 0..60
            int gr = row0 + r;
            float4 xv = (gr < n) ? *(const float4*)&X[(long long)gr * 128 + h * 64 + kq]
                                 : make_float4(0.f, 0.f, 0.f, 0.f);
            float xe[4] = {xv.x, xv.y, xv.z, xv.w};
            float xl[4];
            #pragma unroll
            for (int q = 0; q < 4; q++)
                xl[q] = xe[q] - __half2float(__float2half_rn(xe[q]));
            int k2 = kq >> 1;                  // 0..30 (local)
            sA[(k2 + 0) * SPU + r] = make_uint2(packh2(xe[0], xe[1]), packh2(xl[0], xl[1]));
            sA[(k2 + 1) * SPU + r] = make_uint2(packh2(xe[2], xe[3]), packh2(xl[2], xl[3]));
        }
        __syncthreads();

        #pragma unroll
        for (int kt = 0; kt < 4; kt++) {
            const int ka = kt * 8;             // local k2 base for A
            const int kb = h * 32 + kt * 8;    // global k2 base for B
            uint32_t ahi[2][4], alo[2][4];
            #pragma unroll
            for (int mt = 0; mt < 2; mt++) {
                int r = warpRow * 32 + mt * 16 + lr;
                uint2 v0 = sA[(ka + lq) * SPU + r];
                uint2 v1 = sA[(ka + lq) * SPU + r + 8];
                uint2 v2 = sA[(ka + lq + 4) * SPU + r];
                uint2 v3 = sA[(ka + lq + 4) * SPU + r + 8];
                ahi[mt][0] = v0.x; alo[mt][0] = v0.y;
                ahi[mt][1] = v1.x; alo[mt][1] = v1.y;
                ahi[mt][2] = v2.x; alo[mt][2] = v2.y;
                ahi[mt][3] = v3.x; alo[mt][3] = v3.y;
            }
            #pragma unroll
            for (int nt = 0; nt < 8; nt++) {
                int col = warpCol * 64 + nt * 8 + lr;
                uint2 w0 = sB[(kb + lq) * SPU + col];
                uint2 w1 = sB[(kb + lq + 4) * SPU + col];
                #pragma unroll
                for (int mt = 0; mt < 2; mt++) {
                    mma_f16(c[mt][nt], ahi[mt][0], ahi[mt][1], ahi[mt][2], ahi[mt][3], w0.x, w1.x);
                    mma_f16(c[mt][nt], ahi[mt][0], ahi[mt][1], ahi[mt][2], ahi[mt][3], w0.y, w1.y);
                    mma_f16(c[mt][nt], alo[mt][0], alo[mt][1], alo[mt][2], alo[mt][3], w0.x, w1.x);
                }
            }
        }
        if (h == 0) __syncthreads();
    }

    #pragma unroll
    for (int mt = 0; mt < 2; mt++) {
        #pragma unroll
        for (int h2 = 0; h2 < 2; h2++) {
            int gi = row0 + warpRow * 32 + mt * 16 + lr + h2 * 8;
            if (gi >= n) continue;
            float dv = g_dis[gi];
            #pragma unroll
            for (int nt = 0; nt < 8; nt++) {
                int col = warpCol * 64 + nt * 8 + lq * 2;
                float ox = dv * (c[mt][nt][h2 * 2 + 0] + Bv[col]);
                float oy = dv * (c[mt][nt][h2 * 2 + 1] + Bv[col + 1]);
                *(__half2*)&g_hs[(long long)gi * 128 + col] = __floats2half2_rn(ox, oy);
            }
        }
    }
}

// layers 2-3 GEMM: X already exact fp16 (2 MMAs / product).
// Whole X tile + whole W-split resident in smem; single __syncthreads.
__global__ __launch_bounds__(256) void k_gemm2(const uint2* __restrict__ Wsp,
                                               const float* __restrict__ Bv,
                                               int n) {
    extern __shared__ char smem[];
    uint2*    sB = (uint2*)smem;              // [64][SPU]
    uint32_t* sA = (uint32_t*)(sB + 64 * SPU);// [64][SPU] xhi2

    const int tid  = threadIdx.x;
    const int lane = tid & 31;
    const int wid  = tid >> 5;
    const int warpRow = wid >> 1;
    const int warpCol = wid & 1;
    const int row0 = blockIdx.x * 128;
    const int lr = lane >> 2;
    const int lq = lane & 3;

    #pragma unroll
    for (int it = 0; it < 32; it++) {
        int j = it * 256 + tid;
        int kk2 = j >> 7;
        int col = j & 127;
        sB[kk2 * SPU + col] = Wsp[j];
    }
    #pragma unroll
    for (int it = 0; it < 16; it++) {
        int idx = it * 256 + tid;              // 0..4095
        int r = idx >> 5;                      // 0..127
        int k2 = (idx & 31) * 2;               // 0..62
        uint2 v = make_uint2(0u, 0u);
        int gr = row0 + r;
        if (gr < n)
            v = *(const uint2*)&g_buf[(long long)gr * 128 + k2 * 2];
        sA[(k2 + 0) * SPU + r] = v.x;
        sA[(k2 + 1) * SPU + r] = v.y;
    }
    __syncthreads();

    float c[2][8][4];
    #pragma unroll
    for (int mt = 0; mt < 2; mt++)
        #pragma unroll
        for (int nt = 0; nt < 8; nt++)
            #pragma unroll
            for (int q = 0; q < 4; q++) c[mt][nt][q] = 0.f;

    #pragma unroll
    for (int kt = 0; kt < 8; kt++) {
        const int kb = kt * 8;
        uint32_t a[2][4];
        #pragma unroll
        for (int mt = 0; mt < 2; mt++) {
            int r = warpRow * 32 + mt * 16 + lr;
            a[mt][0] = sA[(kb + lq) * SPU + r];
            a[mt][1] = sA[(kb + lq) * SPU + r + 8];
            a[mt][2] = sA[(kb + lq + 4) * SPU + r];
            a[mt][3] = sA[(kb + lq + 4) * SPU + r + 8];
        }
        #pragma unroll
        for (int nt = 0; nt < 8; nt++) {
            int col = warpCol * 64 + nt * 8 + lr;
            uint2 w0 = sB[(kb + lq) * SPU + col];
            uint2 w1 = sB[(kb + lq + 4) * SPU + col];
            #pragma unroll
            for (int mt = 0; mt < 2; mt++) {
                mma_f16(c[mt][nt], a[mt][0], a[mt][1], a[mt][2], a[mt][3], w0.x, w1.x);
                mma_f16(c[mt][nt], a[mt][0], a[mt][1], a[mt][2], a[mt][3], w0.y, w1.y);
            }
        }
    }

    #pragma unroll
    for (int mt = 0; mt < 2; mt++) {
        #pragma unroll
        for (int h2 = 0; h2 < 2; h2++) {
            int gi = row0 + warpRow * 32 + mt * 16 + lr + h2 * 8;
            if (gi >= n) continue;
            float dv = g_dis[gi];
            #pragma unroll
            for (int nt = 0; nt < 8; nt++) {
                int col = warpCol * 64 + nt * 8 + lq * 2;
                float ox = dv * (c[mt][nt][h2 * 2 + 0] + Bv[col]);
                float oy = dv * (c[mt][nt][h2 * 2 + 1] + Bv[col + 1]);
                *(__half2*)&g_hs[(long long)gi * 128 + col] = __floats2half2_rn(ox, oy);
            }
        }
    }
}

// --------------------------------------------------------------------------
// Pull aggregation fused with finalize (fp16 gather via LDG.64, fp32 accum)
// --------------------------------------------------------------------------
__device__ __forceinline__ void acc_row(float& ax, float& ay, float& az, float& aw,
                                        int src, int lane) {
    uint2 v = __ldg((const uint2*)(g_hs + ((long long)src << 7)) + lane);
    float2 f0 = __half22float2(*reinterpret_cast<__half2*>(&v.x));
    float2 f1 = __half22float2(*reinterpret_cast<__half2*>(&v.y));
    ax += f0.x; ay += f0.y; az += f1.x; aw += f1.y;
}

__global__ __launch_bounds__(256) void k_agg(float* __restrict__ dst,
                                             int to_buf, int n) {
    const int node = blockIdx.x * 8 + (threadIdx.x >> 5);
    if (node >= n) return;
    const int lane = threadIdx.x & 31;

    const int beg = g_off[node];
    const int end = g_off[node + 1];

    float ax, ay, az, aw;
    {
        uint2 v = *((const uint2*)(g_hs + ((long long)node << 7)) + lane);
        float2 f0 = __half22float2(*reinterpret_cast<__half2*>(&v.x));
        float2 f1 = __half22float2(*reinterpret_cast<__half2*>(&v.y));
        ax = f0.x; ay = f0.y; az = f1.x; aw = f1.y;
    }

    int j = beg;
    for (; j + 8 <= end; j += 8) {
        int i0 = __ldg(&g_csr[j + 0]);
        int i1 = __ldg(&g_csr[j + 1]);
        int i2 = __ldg(&g_csr[j + 2]);
        int i3 = __ldg(&g_csr[j + 3]);
        int i4 = __ldg(&g_csr[j + 4]);
        int i5 = __ldg(&g_csr[j + 5]);
        int i6 = __ldg(&g_csr[j + 6]);
        int i7 = __ldg(&g_csr[j + 7]);
        acc_row(ax, ay, az, aw, i0, lane);
        acc_row(ax, ay, az, aw, i1, lane);
        acc_row(ax, ay, az, aw, i2, lane);
        acc_row(ax, ay, az, aw, i3, lane);
        acc_row(ax, ay, az, aw, i4, lane);
        acc_row(ax, ay, az, aw, i5, lane);
        acc_row(ax, ay, az, aw, i6, lane);
        acc_row(ax, ay, az, aw, i7, lane);
    }
    for (; j < end; j++) {
        int i0 = __ldg(&g_csr[j]);
        acc_row(ax, ay, az, aw, i0, lane);
    }

    const float dv = g_dis[node];
    ax = fmaxf(dv * ax, 0.f);
    ay = fmaxf(dv * ay, 0.f);
    az = fmaxf(dv * az, 0.f);
    aw = fmaxf(dv * aw, 0.f);

    if (to_buf) {
        uint2 o = make_uint2(packh2(ax, ay), packh2(az, aw));
        *((uint2*)(g_buf + ((long long)node << 7)) + lane) = o;
    } else {
        *(float4*)(&dst[((long long)node << 7) + lane * 4]) = make_float4(ax, ay, az, aw);
    }
}

// --------------------------------------------------------------------------
extern "C" void kernel_launch(void* const* d_in, const int* in_sizes, int n_in,
                              void* d_out, int out_size) {
    const float* x  = (const float*)d_in[0];
    const void*  ep = d_in[1];
    const float* W1 = (const float*)d_in[2];
    const float* b1 = (const float*)d_in[3];
    const float* W2 = (const float*)d_in[4];
    const float* b2 = (const float*)d_in[5];
    const float* W3 = (const float*)d_in[6];
    const float* b3 = (const float*)d_in[7];
    float* out = (float*)d_out;

    const int n = in_sizes[0] / D;
    const long long E = (long long)in_sizes[1] / 2;

    const int tb = 256;
    const int nb_n    = (n + tb - 1) / tb;
    const int nb_e    = (int)((E + tb - 1) / tb);
    const int nb_gemm = (n + 127) / 128;
    const int nb_agg  = (n + 7) / 8;

    uint2* wsp;
    cudaGetSymbolAddress((void**)&wsp, g_wsp);
    cudaFuncSetAttribute(k_gemm1, cudaFuncAttributeMaxDynamicSharedMemorySize, GEMM_SMEM);
    cudaFuncSetAttribute(k_gemm2, cudaFuncAttributeMaxDynamicSharedMemorySize, GEMM_SMEM);

    k_pre<<<nb_n, tb>>>((const int*)ep, n, W1, W2, W3);
    k_count<<<nb_e, tb>>>(ep, E);
    k_scan_dis<<<1, 1024>>>(n);
    k_gemm1<<<nb_gemm, 256, GEMM_SMEM>>>(x, wsp, b1, n);   // 4th launch -> profiled
    k_fill<<<nb_e, tb>>>(ep, E);
    k_agg<<<nb_agg, 256>>>(out, 1, n);
    k_gemm2<<<nb_gemm, 256, GEMM_SMEM>>>(wsp + 8192, b2, n);
    k_agg<<<nb_agg, 256>>>(out, 1, n);
    k_gemm2<<<nb_gemm, 256, GEMM_SMEM>>>(wsp + 2 * 8192, b3, n);
    k_agg<<<nb_agg, 256>>>(out, 0, n);
}

// round 8
// speedup vs baseline: 1.0066x; 1.0066x over previous
#include <cuda_runtime.h>
#include <cuda_fp16.h>
#include <cstdint>

#define D 128
#define MAXN 100096
#define EMAX 1700000
#define SPU 132

__device__ __half g_hs [MAXN * D];    // fp16: dis[i] * (x W^T + b)
__device__ __half g_buf[MAXN * D];    // fp16 layer output -> next layer input
__device__ uint2  g_wsp[3][64 * 128]; // pre-split W: {hi2, lo2} per (k2, col)
__device__ int    g_deg[MAXN];
__device__ int    g_indeg[MAXN];
__device__ int    g_off[MAXN + 1];
__device__ int    g_pos[MAXN];
__device__ int    g_csr[EMAX];
__device__ float  g_dis[MAXN];
__device__ int    g_is64;

__device__ __forceinline__ uint32_t packh2(float a, float b) {
    __half2 h = __floats2half2_rn(a, b);
    return *reinterpret_cast<uint32_t*>(&h);
}

// --------------------------------------------------------------------------
// preamble 1: dtype detect + init deg/indeg + W pre-split (all 3 layers)
// --------------------------------------------------------------------------
__global__ void k_pre(const int* __restrict__ e32, int n,
                      const float* __restrict__ W1,
                      const float* __restrict__ W2,
                      const float* __restrict__ W3) {
    int i = blockIdx.x * blockDim.x + threadIdx.x;
    if (i == 0) {
        int nz = 0;
        #pragma unroll 1
        for (int q = 0; q < 64; q++) nz += (e32[2 * q + 1] != 0);
        g_is64 = (nz == 0) ? 1 : 0;
    }
    if (i < n) { g_deg[i] = 1; g_indeg[i] = 0; }
    if (i < 3 * 8192) {
        const int l   = i >> 13;
        const int rem = i & 8191;
        const int k2  = rem >> 7;
        const int col = rem & 127;
        const float* W = (l == 0) ? W1 : (l == 1) ? W2 : W3;
        float w0 = W[col * 128 + 2 * k2];
        float w1 = W[col * 128 + 2 * k2 + 1];
        float h0f = __half2float(__float2half_rn(w0));
        float h1f = __half2float(__float2half_rn(w1));
        g_wsp[l][k2 * 128 + col] =
            make_uint2(packh2(w0, w1), packh2(w0 - h0f, w1 - h1f));
    }
}

__global__ void k_count(const void* __restrict__ ep, long long E) {
    long long e = (long long)blockIdx.x * blockDim.x + threadIdx.x;
    if (e >= E) return;
    int r, c;
    if (g_is64) {
        const long long* p = (const long long*)ep;
        r = (int)p[e]; c = (int)p[e + E];
    } else {
        const int* p = (const int*)ep;
        r = p[e]; c = p[e + E];
    }
    atomicAdd(&g_deg[r], 1);
    atomicAdd(&g_indeg[c], 1);
}

__global__ __launch_bounds__(1024) void k_scan_dis(int n) {
    __shared__ int s[1024];
    const int t = threadIdx.x;
    const int chunk = (n + 1023) / 1024;
    const int start = t * chunk;
    const int end = min(start + chunk, n);
    int sum = 0;
    for (int i = start; i < end; i++) {
        sum += g_indeg[i];
        g_dis[i] = rsqrtf((float)g_deg[i]);
    }
    s[t] = sum;
    __syncthreads();
    for (int o = 1; o < 1024; o <<= 1) {
        int v = (t >= o) ? s[t - o] : 0;
        __syncthreads();
        s[t] += v;
        __syncthreads();
    }
    int run = (t == 0) ? 0 : s[t - 1];
    for (int i = start; i < end; i++) {
        g_off[i] = run;
        g_pos[i] = run;
        run += g_indeg[i];
    }
    if (t == 1023) g_off[n] = s[1023];
}

__global__ void k_fill(const void* __restrict__ ep, long long E) {
    long long e = (long long)blockIdx.x * blockDim.x + threadIdx.x;
    if (e >= E) return;
    int r, c;
    if (g_is64) {
        const long long* p = (const long long*)ep;
        r = (int)p[e]; c = (int)p[e + E];
    } else {
        const int* p = (const int*)ep;
        r = p[e]; c = p[e + E];
    }
    int p = atomicAdd(&g_pos[c], 1);
    g_csr[p] = r;
}

// --------------------------------------------------------------------------
// fp16 m16n8k16 MMA (fp32 accumulate)
// --------------------------------------------------------------------------
__device__ __forceinline__ void mma_f16(float c[4],
                                        uint32_t a0, uint32_t a1, uint32_t a2, uint32_t a3,
                                        uint32_t b0, uint32_t b1) {
    asm volatile(
        "mma.sync.aligned.m16n8k16.row.col.f32.f16.f16.f32 "
        "{%0,%1,%2,%3}, {%4,%5,%6,%7}, {%8,%9}, {%0,%1,%2,%3};"
        : "+f"(c[0]), "+f"(c[1]), "+f"(c[2]), "+f"(c[3])
        : "r"(a0), "r"(a1), "r"(a2), "r"(a3), "r"(b0), "r"(b1));
}

// layer-1 GEMM (R6 structure): fp32 X, hi/lo split, BK=16 per stage
__global__ __launch_bounds__(256) void k_gemm1(const float* __restrict__ X,
                                               const uint2* __restrict__ Wsp,
                                               const float* __restrict__ Bv,
                                               int n) {
    __shared__ uint2 sA[8][SPU];   // {xhi2, xlo2} per (k2, row)
    __shared__ uint2 sB[8][SPU];   // {whi2, wlo2} per (k2, col)

    const int tid  = threadIdx.x;
    const int lane = tid & 31;
    const int wid  = tid >> 5;
    const int warpRow = wid >> 1;
    const int warpCol = wid & 1;
    const int row0 = blockIdx.x * 128;
    const int lr = lane >> 2;
    const int lq = lane & 3;

    float c[2][8][4];
    #pragma unroll
    for (int mt = 0; mt < 2; mt++)
        #pragma unroll
        for (int nt = 0; nt < 8; nt++)
            #pragma unroll
            for (int q = 0; q < 4; q++) c[mt][nt][q] = 0.f;

    for (int k0 = 0; k0 < 128; k0 += 16) {
        const int k02 = k0 >> 1;
        #pragma unroll
        for (int it = 0; it < 2; it++) {
            int idx = it * 256 + tid;
            int r = idx >> 2;
            int kq = (idx & 3) * 4;
            int gr = row0 + r;
            float4 xv = (gr < n) ? *(const float4*)&X[(long long)gr * 128 + k0 + kq]
                                 : make_float4(0.f, 0.f, 0.f, 0.f);
            float xe[4] = {xv.x, xv.y, xv.z, xv.w};
            float xl[4];
            #pragma unroll
            for (int q = 0; q < 4; q++)
                xl[q] = xe[q] - __half2float(__float2half_rn(xe[q]));
            int k2 = kq >> 1;
            sA[k2 + 0][r] = make_uint2(packh2(xe[0], xe[1]), packh2(xl[0], xl[1]));
            sA[k2 + 1][r] = make_uint2(packh2(xe[2], xe[3]), packh2(xl[2], xl[3]));
        }
        #pragma unroll
        for (int it = 0; it < 4; it++) {
            int j = it * 256 + tid;
            int kk2 = j >> 7;
            int col = j & 127;
            sB[kk2][col] = Wsp[(k02 + kk2) * 128 + col];
        }
        __syncthreads();

        uint32_t ahi[2][4], alo[2][4];
        #pragma unroll
        for (int mt = 0; mt < 2; mt++) {
            int r = warpRow * 32 + mt * 16 + lr;
            #pragma unroll
            for (int kg = 0; kg < 2; kg++) {
                uint2 v0 = sA[kg * 4 + lq][r];
                uint2 v1 = sA[kg * 4 + lq][r + 8];
                ahi[mt][kg * 2 + 0] = v0.x; alo[mt][kg * 2 + 0] = v0.y;
                ahi[mt][kg * 2 + 1] = v1.x; alo[mt][kg * 2 + 1] = v1.y;
            }
        }
        #pragma unroll
        for (int nt = 0; nt < 8; nt++) {
            int col = warpCol * 64 + nt * 8 + lr;
            uint2 w0 = sB[0 * 4 + lq][col];
            uint2 w1 = sB[1 * 4 + lq][col];
            #pragma unroll
            for (int mt = 0; mt < 2; mt++) {
                mma_f16(c[mt][nt], ahi[mt][0], ahi[mt][1], ahi[mt][2], ahi[mt][3], w0.x, w1.x);
                mma_f16(c[mt][nt], ahi[mt][0], ahi[mt][1], ahi[mt][2], ahi[mt][3], w0.y, w1.y);
                mma_f16(c[mt][nt], alo[mt][0], alo[mt][1], alo[mt][2], alo[mt][3], w0.x, w1.x);
            }
        }
        __syncthreads();
    }

    #pragma unroll
    for (int mt = 0; mt < 2; mt++) {
        #pragma unroll
        for (int h2 = 0; h2 < 2; h2++) {
            int gi = row0 + warpRow * 32 + mt * 16 + lr + h2 * 8;
            if (gi >= n) continue;
            float dv = g_dis[gi];
            #pragma unroll
            for (int nt = 0; nt < 8; nt++) {
                int col = warpCol * 64 + nt * 8 + lq * 2;
                float ox = dv * (c[mt][nt][h2 * 2 + 0] + Bv[col]);
                float oy = dv * (c[mt][nt][h2 * 2 + 1] + Bv[col + 1]);
                *(__half2*)&g_hs[(long long)gi * 128 + col] = __floats2half2_rn(ox, oy);
            }
        }
    }
}

// layers 2-3 GEMM (R6 structure): X exact fp16, 2 MMAs / product
__global__ __launch_bounds__(256) void k_gemm2(const uint2* __restrict__ Wsp,
                                               const float* __restrict__ Bv,
                                               int n) {
    __shared__ uint32_t sA[8][SPU];
    __shared__ uint2    sB[8][SPU];

    const int tid  = threadIdx.x;
    const int lane = tid & 31;
    const int wid  = tid >> 5;
    const int warpRow = wid >> 1;
    const int warpCol = wid & 1;
    const int row0 = blockIdx.x * 128;
    const int lr = lane >> 2;
    const int lq = lane & 3;

    float c[2][8][4];
    #pragma unroll
    for (int mt = 0; mt < 2; mt++)
        #pragma unroll
        for (int nt = 0; nt < 8; nt++)
            #pragma unroll
            for (int q = 0; q < 4; q++) c[mt][nt][q] = 0.f;

    for (int k0 = 0; k0 < 128; k0 += 16) {
        const int k02 = k0 >> 1;
        #pragma unroll
        for (int it = 0; it < 2; it++) {
            int idx = it * 256 + tid;
            int r = idx >> 2;
            int kq = (idx & 3) * 4;
            int gr = row0 + r;
            uint2 v = make_uint2(0u, 0u);
            if (gr < n)
                v = *(const uint2*)&g_buf[(long long)gr * 128 + k0 + kq];
            int k2 = kq >> 1;
            sA[k2 + 0][r] = v.x;
            sA[k2 + 1][r] = v.y;
        }
        #pragma unroll
        for (int it = 0; it < 4; it++) {
            int j = it * 256 + tid;
            int kk2 = j >> 7;
            int col = j & 127;
            sB[kk2][col] = Wsp[(k02 + kk2) * 128 + col];
        }
        __syncthreads();

        uint32_t a[2][4];
        #pragma unroll
        for (int mt = 0; mt < 2; mt++) {
            int r = warpRow * 32 + mt * 16 + lr;
            #pragma unroll
            for (int kg = 0; kg < 2; kg++) {
                a[mt][kg * 2 + 0] = sA[kg * 4 + lq][r];
                a[mt][kg * 2 + 1] = sA[kg * 4 + lq][r + 8];
            }
        }
        #pragma unroll
        for (int nt = 0; nt < 8; nt++) {
            int col = warpCol * 64 + nt * 8 + lr;
            uint2 w0 = sB[0 * 4 + lq][col];
            uint2 w1 = sB[1 * 4 + lq][col];
            #pragma unroll
            for (int mt = 0; mt < 2; mt++) {
                mma_f16(c[mt][nt], a[mt][0], a[mt][1], a[mt][2], a[mt][3], w0.x, w1.x);
                mma_f16(c[mt][nt], a[mt][0], a[mt][1], a[mt][2], a[mt][3], w0.y, w1.y);
            }
        }
        __syncthreads();
    }

    #pragma unroll
    for (int mt = 0; mt < 2; mt++) {
        #pragma unroll
        for (int h2 = 0; h2 < 2; h2++) {
            int gi = row0 + warpRow * 32 + mt * 16 + lr + h2 * 8;
            if (gi >= n) continue;
            float dv = g_dis[gi];
            #pragma unroll
            for (int nt = 0; nt < 8; nt++) {
                int col = warpCol * 64 + nt * 8 + lq * 2;
                float ox = dv * (c[mt][nt][h2 * 2 + 0] + Bv[col]);
                float oy = dv * (c[mt][nt][h2 * 2 + 1] + Bv[col + 1]);
                *(__half2*)&g_hs[(long long)gi * 128 + col] = __floats2half2_rn(ox, oy);
            }
        }
    }
}

// --------------------------------------------------------------------------
// Pull aggregation v3: one warp per node; two half-warps process two edges
// per step; each lane loads uint4 (8 halves). Final shfl_xor(16) combine.
// --------------------------------------------------------------------------
__global__ __launch_bounds__(256) void k_agg(float* __restrict__ dst,
                                             int to_buf, int n) {
    const int node = blockIdx.x * 8 + (threadIdx.x >> 5);
    if (node >= n) return;
    const int lane = threadIdx.x & 31;
    const int hl = lane >> 4;     // 0: even edges, 1: odd edges
    const int sl = lane & 15;     // column group: halves [sl*8, sl*8+8)

    const int beg = g_off[node];
    const int end = g_off[node + 1];

    const uint4* hsb = (const uint4*)g_hs;   // row i at i*16 + sl

    float a0 = 0.f, a1 = 0.f, a2 = 0.f, a3 = 0.f,
          a4 = 0.f, a5 = 0.f, a6 = 0.f, a7 = 0.f;

    // self-loop: only half 0 contributes (avoid double count after combine)
    if (hl == 0) {
        uint4 v = hsb[(long long)node * 16 + sl];
        float2 f;
        f = __half22float2(*reinterpret_cast<__half2*>(&v.x)); a0 = f.x; a1 = f.y;
        f = __half22float2(*reinterpret_cast<__half2*>(&v.y)); a2 = f.x; a3 = f.y;
        f = __half22float2(*reinterpret_cast<__half2*>(&v.z)); a4 = f.x; a5 = f.y;
        f = __half22float2(*reinterpret_cast<__half2*>(&v.w)); a6 = f.x; a7 = f.y;
    }

    int j = beg + hl;
    // unrolled: this half processes j, j+2, j+4, j+6 (valid while j+6 <= end-1)
    for (; j + 6 < end; j += 8) {
        int i0 = __ldg(&g_csr[j + 0]);
        int i1 = __ldg(&g_csr[j + 2]);
        int i2 = __ldg(&g_csr[j + 4]);
        int i3 = __ldg(&g_csr[j + 6]);
        uint4 v0 = __ldg(&hsb[(long long)i0 * 16 + sl]);
        uint4 v1 = __ldg(&hsb[(long long)i1 * 16 + sl]);
        uint4 v2 = __ldg(&hsb[(long long)i2 * 16 + sl]);
        uint4 v3 = __ldg(&hsb[(long long)i3 * 16 + sl]);
        float2 f;
        f = __half22float2(*reinterpret_cast<__half2*>(&v0.x)); a0 += f.x; a1 += f.y;
        f = __half22float2(*reinterpret_cast<__half2*>(&v0.y)); a2 += f.x; a3 += f.y;
        f = __half22float2(*reinterpret_cast<__half2*>(&v0.z)); a4 += f.x; a5 += f.y;
        f = __half22float2(*reinterpret_cast<__half2*>(&v0.w)); a6 += f.x; a7 += f.y;
        f = __half22float2(*reinterpret_cast<__half2*>(&v1.x)); a0 += f.x; a1 += f.y;
        f = __half22float2(*reinterpret_cast<__half2*>(&v1.y)); a2 += f.x; a3 += f.y;
        f = __half22float2(*reinterpret_cast<__half2*>(&v1.z)); a4 += f.x; a5 += f.y;
        f = __half22float2(*reinterpret_cast<__half2*>(&v1.w)); a6 += f.x; a7 += f.y;
        f = __half22float2(*reinterpret_cast<__half2*>(&v2.x)); a0 += f.x; a1 += f.y;
        f = __half22float2(*reinterpret_cast<__half2*>(&v2.y)); a2 += f.x; a3 += f.y;
        f = __half22float2(*reinterpret_cast<__half2*>(&v2.z)); a4 += f.x; a5 += f.y;
        f = __half22float2(*reinterpret_cast<__half2*>(&v2.w)); a6 += f.x; a7 += f.y;
        f = __half22float2(*reinterpret_cast<__half2*>(&v3.x)); a0 += f.x; a1 += f.y;
        f = __half22float2(*reinterpret_cast<__half2*>(&v3.y)); a2 += f.x; a3 += f.y;
        f = __half22float2(*reinterpret_cast<__half2*>(&v3.z)); a4 += f.x; a5 += f.y;
        f = __half22float2(*reinterpret_cast<__half2*>(&v3.w)); a6 += f.x; a7 += f.y;
    }
    for (; j < end; j += 2) {
        int i0 = __ldg(&g_csr[j]);
        uint4 v0 = __ldg(&hsb[(long long)i0 * 16 + sl]);
        float2 f;
        f = __half22float2(*reinterpret_cast<__half2*>(&v0.x)); a0 += f.x; a1 += f.y;
        f = __half22float2(*reinterpret_cast<__half2*>(&v0.y)); a2 += f.x; a3 += f.y;
        f = __half22float2(*reinterpret_cast<__half2*>(&v0.z)); a4 += f.x; a5 += f.y;
        f = __half22float2(*reinterpret_cast<__half2*>(&v0.w)); a6 += f.x; a7 += f.y;
    }

    // combine halves
    a0 += __shfl_xor_sync(0xffffffffu, a0, 16);
    a1 += __shfl_xor_sync(0xffffffffu, a1, 16);
    a2 += __shfl_xor_sync(0xffffffffu, a2, 16);
    a3 += __shfl_xor_sync(0xffffffffu, a3, 16);
    a4 += __shfl_xor_sync(0xffffffffu, a4, 16);
    a5 += __shfl_xor_sync(0xffffffffu, a5, 16);
    a6 += __shfl_xor_sync(0xffffffffu, a6, 16);
    a7 += __shfl_xor_sync(0xffffffffu, a7, 16);

    const float dv = g_dis[node];
    a0 = fmaxf(dv * a0, 0.f); a1 = fmaxf(dv * a1, 0.f);
    a2 = fmaxf(dv * a2, 0.f); a3 = fmaxf(dv * a3, 0.f);
    a4 = fmaxf(dv * a4, 0.f); a5 = fmaxf(dv * a5, 0.f);
    a6 = fmaxf(dv * a6, 0.f); a7 = fmaxf(dv * a7, 0.f);

    if (hl == 0) {
        if (to_buf) {
            uint4 o;
            o.x = packh2(a0, a1); o.y = packh2(a2, a3);
            o.z = packh2(a4, a5); o.w = packh2(a6, a7);
            ((uint4*)g_buf)[(long long)node * 16 + sl] = o;
        } else {
            float4* op = (float4*)&dst[((long long)node << 7) + sl * 8];
            op[0] = make_float4(a0, a1, a2, a3);
            op[1] = make_float4(a4, a5, a6, a7);
        }
    }
}

// --------------------------------------------------------------------------
extern "C" void kernel_launch(void* const* d_in, const int* in_sizes, int n_in,
                              void* d_out, int out_size) {
    const float* x  = (const float*)d_in[0];
    const void*  ep = d_in[1];
    const float* W1 = (const float*)d_in[2];
    const float* b1 = (const float*)d_in[3];
    const float* W2 = (const float*)d_in[4];
    const float* b2 = (const float*)d_in[5];
    const float* W3 = (const float*)d_in[6];
    const float* b3 = (const float*)d_in[7];
    float* out = (float*)d_out;

    const int n = in_sizes[0] / D;
    const long long E = (long long)in_sizes[1] / 2;

    const int tb = 256;
    const int nb_n    = (n + tb - 1) / tb;
    const int nb_e    = (int)((E + tb - 1) / tb);
    const int nb_gemm = (n + 127) / 128;
    const int nb_agg  = (n + 7) / 8;

    uint2* wsp;
    cudaGetSymbolAddress((void**)&wsp, g_wsp);

    k_pre<<<nb_n, tb>>>((const int*)ep, n, W1, W2, W3);
    k_count<<<nb_e, tb>>>(ep, E);
    k_scan_dis<<<1, 1024>>>(n);
    k_gemm1<<<nb_gemm, 256>>>(x, wsp, b1, n);   // profiled slot
    k_fill<<<nb_e, tb>>>(ep, E);
    k_agg<<<nb_agg, 256>>>(out, 1, n);
    k_gemm2<<<nb_gemm, 256>>>(wsp + 8192, b2, n);
    k_agg<<<nb_agg, 256>>>(out, 1, n);
    k_gemm2<<<nb_gemm, 256>>>(wsp + 2 * 8192, b3, n);
    k_agg<<<nb_agg, 256>>>(out, 0, n);
}

// round 9
// speedup vs baseline: 1.3937x; 1.3845x over previous
#include <cuda_runtime.h>
#include <cuda_fp16.h>
#include <cstdint>

#define D 128
#define MAXN 100096
#define EMAX 1700000
#define SPU 132

__device__ __half g_hs [MAXN * D];    // fp16: dis[i] * (x W^T + b)
__device__ __half g_buf[MAXN * D];    // fp16 layer output -> next layer input
__device__ uint2  g_wsp[3][64 * 128]; // pre-split W: {hi2, lo2} per (k2, col)
__device__ int    g_deg[MAXN];
__device__ int    g_indeg[MAXN];
__device__ int    g_off[MAXN + 1];
__device__ int    g_pos[MAXN];
__device__ int    g_csr[EMAX];
__device__ float  g_dis[MAXN];
__device__ int    g_is64;

__device__ __forceinline__ uint32_t packh2(float a, float b) {
    __half2 h = __floats2half2_rn(a, b);
    return *reinterpret_cast<uint32_t*>(&h);
}

// --------------------------------------------------------------------------
__global__ void k_pre(const int* __restrict__ e32, int n,
                      const float* __restrict__ W1,
                      const float* __restrict__ W2,
                      const float* __restrict__ W3) {
    int i = blockIdx.x * blockDim.x + threadIdx.x;
    if (i == 0) {
        int nz = 0;
        #pragma unroll 1
        for (int q = 0; q < 64; q++) nz += (e32[2 * q + 1] != 0);
        g_is64 = (nz == 0) ? 1 : 0;
    }
    if (i < n) { g_deg[i] = 1; g_indeg[i] = 0; }
    if (i < 3 * 8192) {
        const int l   = i >> 13;
        const int rem = i & 8191;
        const int k2  = rem >> 7;
        const int col = rem & 127;
        const float* W = (l == 0) ? W1 : (l == 1) ? W2 : W3;
        float w0 = W[col * 128 + 2 * k2];
        float w1 = W[col * 128 + 2 * k2 + 1];
        float h0f = __half2float(__float2half_rn(w0));
        float h1f = __half2float(__float2half_rn(w1));
        g_wsp[l][k2 * 128 + col] =
            make_uint2(packh2(w0, w1), packh2(w0 - h0f, w1 - h1f));
    }
}

__global__ void k_count(const void* __restrict__ ep, long long E) {
    long long e = (long long)blockIdx.x * blockDim.x + threadIdx.x;
    if (e >= E) return;
    int r, c;
    if (g_is64) {
        const long long* p = (const long long*)ep;
        r = (int)p[e]; c = (int)p[e + E];
    } else {
        const int* p = (const int*)ep;
        r = p[e]; c = p[e + E];
    }
    atomicAdd(&g_deg[r], 1);
    atomicAdd(&g_indeg[c], 1);
}

__global__ void k_dis(int n) {
    int i = blockIdx.x * blockDim.x + threadIdx.x;
    if (i < n) g_dis[i] = rsqrtf((float)g_deg[i]);
}

__global__ __launch_bounds__(1024) void k_scan(int n) {
    __shared__ int s[1024];
    const int t = threadIdx.x;
    const int chunk = (n + 1023) / 1024;
    const int start = t * chunk;
    const int end = min(start + chunk, n);
    int sum = 0;
    for (int i = start; i < end; i++) sum += g_indeg[i];
    s[t] = sum;
    __syncthreads();
    for (int o = 1; o < 1024; o <<= 1) {
        int v = (t >= o) ? s[t - o] : 0;
        __syncthreads();
        s[t] += v;
        __syncthreads();
    }
    int run = (t == 0) ? 0 : s[t - 1];
    for (int i = start; i < end; i++) {
        g_off[i] = run;
        g_pos[i] = run;
        run += g_indeg[i];
    }
    if (t == 1023) g_off[n] = s[1023];
}

__global__ void k_fill(const void* __restrict__ ep, long long E) {
    long long e = (long long)blockIdx.x * blockDim.x + threadIdx.x;
    if (e >= E) return;
    int r, c;
    if (g_is64) {
        const long long* p = (const long long*)ep;
        r = (int)p[e]; c = (int)p[e + E];
    } else {
        const int* p = (const int*)ep;
        r = p[e]; c = p[e + E];
    }
    int p = atomicAdd(&g_pos[c], 1);
    g_csr[p] = r;
}

// --------------------------------------------------------------------------
__device__ __forceinline__ void mma_f16(float c[4],
                                        uint32_t a0, uint32_t a1, uint32_t a2, uint32_t a3,
                                        uint32_t b0, uint32_t b1) {
    asm volatile(
        "mma.sync.aligned.m16n8k16.row.col.f32.f16.f16.f32 "
        "{%0,%1,%2,%3}, {%4,%5,%6,%7}, {%8,%9}, {%0,%1,%2,%3};"
        : "+f"(c[0]), "+f"(c[1]), "+f"(c[2]), "+f"(c[3])
        : "r"(a0), "r"(a1), "r"(a2), "r"(a3), "r"(b0), "r"(b1));
}

// layer-1 GEMM: fp32 X, hi/lo split, BK=16 per stage (R6/R8 structure, 60us)
__global__ __launch_bounds__(256) void k_gemm1(const float* __restrict__ X,
                                               const uint2* __restrict__ Wsp,
                                               const float* __restrict__ Bv,
                                               int n) {
    __shared__ uint2 sA[8][SPU];
    __shared__ uint2 sB[8][SPU];

    const int tid  = threadIdx.x;
    const int lane = tid & 31;
    const int wid  = tid >> 5;
    const int warpRow = wid >> 1;
    const int warpCol = wid & 1;
    const int row0 = blockIdx.x * 128;
    const int lr = lane >> 2;
    const int lq = lane & 3;

    float c[2][8][4];
    #pragma unroll
    for (int mt = 0; mt < 2; mt++)
        #pragma unroll
        for (int nt = 0; nt < 8; nt++)
            #pragma unroll
            for (int q = 0; q < 4; q++) c[mt][nt][q] = 0.f;

    for (int k0 = 0; k0 < 128; k0 += 16) {
        const int k02 = k0 >> 1;
        #pragma unroll
        for (int it = 0; it < 2; it++) {
            int idx = it * 256 + tid;
            int r = idx >> 2;
            int kq = (idx & 3) * 4;
            int gr = row0 + r;
            float4 xv = (gr < n) ? *(const float4*)&X[(long long)gr * 128 + k0 + kq]
                                 : make_float4(0.f, 0.f, 0.f, 0.f);
            float xe[4] = {xv.x, xv.y, xv.z, xv.w};
            float xl[4];
            #pragma unroll
            for (int q = 0; q < 4; q++)
                xl[q] = xe[q] - __half2float(__float2half_rn(xe[q]));
            int k2 = kq >> 1;
            sA[k2 + 0][r] = make_uint2(packh2(xe[0], xe[1]), packh2(xl[0], xl[1]));
            sA[k2 + 1][r] = make_uint2(packh2(xe[2], xe[3]), packh2(xl[2], xl[3]));
        }
        #pragma unroll
        for (int it = 0; it < 4; it++) {
            int j = it * 256 + tid;
            int kk2 = j >> 7;
            int col = j & 127;
            sB[kk2][col] = Wsp[(k02 + kk2) * 128 + col];
        }
        __syncthreads();

        uint32_t ahi[2][4], alo[2][4];
        #pragma unroll
        for (int mt = 0; mt < 2; mt++) {
            int r = warpRow * 32 + mt * 16 + lr;
            #pragma unroll
            for (int kg = 0; kg < 2; kg++) {
                uint2 v0 = sA[kg * 4 + lq][r];
                uint2 v1 = sA[kg * 4 + lq][r + 8];
                ahi[mt][kg * 2 + 0] = v0.x; alo[mt][kg * 2 + 0] = v0.y;
                ahi[mt][kg * 2 + 1] = v1.x; alo[mt][kg * 2 + 1] = v1.y;
            }
        }
        #pragma unroll
        for (int nt = 0; nt < 8; nt++) {
            int col = warpCol * 64 + nt * 8 + lr;
            uint2 w0 = sB[0 * 4 + lq][col];
            uint2 w1 = sB[1 * 4 + lq][col];
            #pragma unroll
            for (int mt = 0; mt < 2; mt++) {
                mma_f16(c[mt][nt], ahi[mt][0], ahi[mt][1], ahi[mt][2], ahi[mt][3], w0.x, w1.x);
                mma_f16(c[mt][nt], ahi[mt][0], ahi[mt][1], ahi[mt][2], ahi[mt][3], w0.y, w1.y);
                mma_f16(c[mt][nt], alo[mt][0], alo[mt][1], alo[mt][2], alo[mt][3], w0.x, w1.x);
            }
        }
        __syncthreads();
    }

    #pragma unroll
    for (int mt = 0; mt < 2; mt++) {
        #pragma unroll
        for (int h2 = 0; h2 < 2; h2++) {
            int gi = row0 + warpRow * 32 + mt * 16 + lr + h2 * 8;
            if (gi >= n) continue;
            float dv = g_dis[gi];
            #pragma unroll
            for (int nt = 0; nt < 8; nt++) {
                int col = warpCol * 64 + nt * 8 + lq * 2;
                float ox = dv * (c[mt][nt][h2 * 2 + 0] + Bv[col]);
                float oy = dv * (c[mt][nt][h2 * 2 + 1] + Bv[col + 1]);
                *(__half2*)&g_hs[(long long)gi * 128 + col] = __floats2half2_rn(ox, oy);
            }
        }
    }
}

// layers 2-3 GEMM: X exact fp16, 2 MMAs / product
__global__ __launch_bounds__(256) void k_gemm2(const uint2* __restrict__ Wsp,
                                               const float* __restrict__ Bv,
                                               int n) {
    __shared__ uint32_t sA[8][SPU];
    __shared__ uint2    sB[8][SPU];

    const int tid  = threadIdx.x;
    const int lane = tid & 31;
    const int wid  = tid >> 5;
    const int warpRow = wid >> 1;
    const int warpCol = wid & 1;
    const int row0 = blockIdx.x * 128;
    const int lr = lane >> 2;
    const int lq = lane & 3;

    float c[2][8][4];
    #pragma unroll
    for (int mt = 0; mt < 2; mt++)
        #pragma unroll
        for (int nt = 0; nt < 8; nt++)
            #pragma unroll
            for (int q = 0; q < 4; q++) c[mt][nt][q] = 0.f;

    for (int k0 = 0; k0 < 128; k0 += 16) {
        const int k02 = k0 >> 1;
        #pragma unroll
        for (int it = 0; it < 2; it++) {
            int idx = it * 256 + tid;
            int r = idx >> 2;
            int kq = (idx & 3) * 4;
            int gr = row0 + r;
            uint2 v = make_uint2(0u, 0u);
            if (gr < n)
                v = *(const uint2*)&g_buf[(long long)gr * 128 + k0 + kq];
            int k2 = kq >> 1;
            sA[k2 + 0][r] = v.x;
            sA[k2 + 1][r] = v.y;
        }
        #pragma unroll
        for (int it = 0; it < 4; it++) {
            int j = it * 256 + tid;
            int kk2 = j >> 7;
            int col = j & 127;
            sB[kk2][col] = Wsp[(k02 + kk2) * 128 + col];
        }
        __syncthreads();

        uint32_t a[2][4];
        #pragma unroll
        for (int mt = 0; mt < 2; mt++) {
            int r = warpRow * 32 + mt * 16 + lr;
            #pragma unroll
            for (int kg = 0; kg < 2; kg++) {
                a[mt][kg * 2 + 0] = sA[kg * 4 + lq][r];
                a[mt][kg * 2 + 1] = sA[kg * 4 + lq][r + 8];
            }
        }
        #pragma unroll
        for (int nt = 0; nt < 8; nt++) {
            int col = warpCol * 64 + nt * 8 + lr;
            uint2 w0 = sB[0 * 4 + lq][col];
            uint2 w1 = sB[1 * 4 + lq][col];
            #pragma unroll
            for (int mt = 0; mt < 2; mt++) {
                mma_f16(c[mt][nt], a[mt][0], a[mt][1], a[mt][2], a[mt][3], w0.x, w1.x);
                mma_f16(c[mt][nt], a[mt][0], a[mt][1], a[mt][2], a[mt][3], w0.y, w1.y);
            }
        }
        __syncthreads();
    }

    #pragma unroll
    for (int mt = 0; mt < 2; mt++) {
        #pragma unroll
        for (int h2 = 0; h2 < 2; h2++) {
            int gi = row0 + warpRow * 32 + mt * 16 + lr + h2 * 8;
            if (gi >= n) continue;
            float dv = g_dis[gi];
            #pragma unroll
            for (int nt = 0; nt < 8; nt++) {
                int col = warpCol * 64 + nt * 8 + lq * 2;
                float ox = dv * (c[mt][nt][h2 * 2 + 0] + Bv[col]);
                float oy = dv * (c[mt][nt][h2 * 2 + 1] + Bv[col + 1]);
                *(__half2*)&g_hs[(long long)gi * 128 + col] = __floats2half2_rn(ox, oy);
            }
        }
    }
}

// --------------------------------------------------------------------------
// Pull aggregation v4: half-warps process alternating edges, 8 gathers in
// flight per half (16 edge slots per outer iteration).
// --------------------------------------------------------------------------
#define ACC8(v)                                                                 \
    do {                                                                        \
        float2 f;                                                               \
        f = __half22float2(*reinterpret_cast<__half2*>(&(v).x)); a0 += f.x; a1 += f.y; \
        f = __half22float2(*reinterpret_cast<__half2*>(&(v).y)); a2 += f.x; a3 += f.y; \
        f = __half22float2(*reinterpret_cast<__half2*>(&(v).z)); a4 += f.x; a5 += f.y; \
        f = __half22float2(*reinterpret_cast<__half2*>(&(v).w)); a6 += f.x; a7 += f.y; \
    } while (0)

__global__ __launch_bounds__(256) void k_agg(float* __restrict__ dst,
                                             int to_buf, int n) {
    const int node = blockIdx.x * 8 + (threadIdx.x >> 5);
    if (node >= n) return;
    const int lane = threadIdx.x & 31;
    const int hl = lane >> 4;
    const int sl = lane & 15;

    const int beg = g_off[node];
    const int end = g_off[node + 1];

    const uint4* hsb = (const uint4*)g_hs;

    float a0 = 0.f, a1 = 0.f, a2 = 0.f, a3 = 0.f,
          a4 = 0.f, a5 = 0.f, a6 = 0.f, a7 = 0.f;

    if (hl == 0) {
        uint4 v = hsb[(long long)node * 16 + sl];
        ACC8(v);
    }

    int j = beg + hl;
    for (; j + 14 < end; j += 16) {
        int i0 = __ldg(&g_csr[j + 0]);
        int i1 = __ldg(&g_csr[j + 2]);
        int i2 = __ldg(&g_csr[j + 4]);
        int i3 = __ldg(&g_csr[j + 6]);
        int i4 = __ldg(&g_csr[j + 8]);
        int i5 = __ldg(&g_csr[j + 10]);
        int i6 = __ldg(&g_csr[j + 12]);
        int i7 = __ldg(&g_csr[j + 14]);
        uint4 v0 = __ldg(&hsb[(long long)i0 * 16 + sl]);
        uint4 v1 = __ldg(&hsb[(long long)i1 * 16 + sl]);
        uint4 v2 = __ldg(&hsb[(long long)i2 * 16 + sl]);
        uint4 v3 = __ldg(&hsb[(long long)i3 * 16 + sl]);
        uint4 v4 = __ldg(&hsb[(long long)i4 * 16 + sl]);
        uint4 v5 = __ldg(&hsb[(long long)i5 * 16 + sl]);
        uint4 v6 = __ldg(&hsb[(long long)i6 * 16 + sl]);
        uint4 v7 = __ldg(&hsb[(long long)i7 * 16 + sl]);
        ACC8(v0); ACC8(v1); ACC8(v2); ACC8(v3);
        ACC8(v4); ACC8(v5); ACC8(v6); ACC8(v7);
    }
    for (; j < end; j += 2) {
        int i0 = __ldg(&g_csr[j]);
        uint4 v0 = __ldg(&hsb[(long long)i0 * 16 + sl]);
        ACC8(v0);
    }

    a0 += __shfl_xor_sync(0xffffffffu, a0, 16);
    a1 += __shfl_xor_sync(0xffffffffu, a1, 16);
    a2 += __shfl_xor_sync(0xffffffffu, a2, 16);
    a3 += __shfl_xor_sync(0xffffffffu, a3, 16);
    a4 += __shfl_xor_sync(0xffffffffu, a4, 16);
    a5 += __shfl_xor_sync(0xffffffffu, a5, 16);
    a6 += __shfl_xor_sync(0xffffffffu, a6, 16);
    a7 += __shfl_xor_sync(0xffffffffu, a7, 16);

    const float dv = g_dis[node];
    a0 = fmaxf(dv * a0, 0.f); a1 = fmaxf(dv * a1, 0.f);
    a2 = fmaxf(dv * a2, 0.f); a3 = fmaxf(dv * a3, 0.f);
    a4 = fmaxf(dv * a4, 0.f); a5 = fmaxf(dv * a5, 0.f);
    a6 = fmaxf(dv * a6, 0.f); a7 = fmaxf(dv * a7, 0.f);

    if (hl == 0) {
        if (to_buf) {
            uint4 o;
            o.x = packh2(a0, a1); o.y = packh2(a2, a3);
            o.z = packh2(a4, a5); o.w = packh2(a6, a7);
            ((uint4*)g_buf)[(long long)node * 16 + sl] = o;
        } else {
            float4* op = (float4*)&dst[((long long)node << 7) + sl * 8];
            op[0] = make_float4(a0, a1, a2, a3);
            op[1] = make_float4(a4, a5, a6, a7);
        }
    }
}

// --------------------------------------------------------------------------
extern "C" void kernel_launch(void* const* d_in, const int* in_sizes, int n_in,
                              void* d_out, int out_size) {
    const float* x  = (const float*)d_in[0];
    const void*  ep = d_in[1];
    const float* W1 = (const float*)d_in[2];
    const float* b1 = (const float*)d_in[3];
    const float* W2 = (const float*)d_in[4];
    const float* b2 = (const float*)d_in[5];
    const float* W3 = (const float*)d_in[6];
    const float* b3 = (const float*)d_in[7];
    float* out = (float*)d_out;

    const int n = in_sizes[0] / D;
    const long long E = (long long)in_sizes[1] / 2;

    const int tb = 256;
    const int nb_n    = (n + tb - 1) / tb;
    const int nb_e    = (int)((E + tb - 1) / tb);
    const int nb_gemm = (n + 127) / 128;
    const int nb_agg  = (n + 7) / 8;

    uint2* wsp;
    cudaGetSymbolAddress((void**)&wsp, g_wsp);

    // side stream + events for CSR-build / GEMM1 overlap (created once; the
    // first call is the uncaptured correctness run, so creation never happens
    // during graph capture)
    static cudaStream_t s2 = nullptr;
    static cudaEvent_t ev1 = nullptr, ev2 = nullptr;
    if (s2 == nullptr) {
        cudaStreamCreateWithFlags(&s2, cudaStreamNonBlocking);
        cudaEventCreateWithFlags(&ev1, cudaEventDisableTiming);
        cudaEventCreateWithFlags(&ev2, cudaEventDisableTiming);
    }

    k_pre<<<nb_n, tb>>>((const int*)ep, n, W1, W2, W3);
    k_count<<<nb_e, tb>>>(ep, E);
    cudaEventRecord(ev1, 0);

    // side stream: CSR offsets + fill (needs indeg from k_count)
    cudaStreamWaitEvent(s2, ev1, 0);
    k_scan<<<1, 1024, 0, s2>>>(n);
    k_fill<<<nb_e, tb, 0, s2>>>(ep, E);
    cudaEventRecord(ev2, s2);

    // main stream: dis + layer-1 GEMM (independent of CSR build)
    k_dis<<<nb_n, tb>>>(n);
    k_gemm1<<<nb_gemm, 256>>>(x, wsp, b1, n);

    // join: aggregation needs the CSR
    cudaStreamWaitEvent(0, ev2, 0);
    k_agg<<<nb_agg, 256>>>(out, 1, n);
    k_gemm2<<<nb_gemm, 256>>>(wsp + 8192, b2, n);
    k_agg<<<nb_agg, 256>>>(out, 1, n);
    k_gemm2<<<nb_gemm, 256>>>(wsp + 2 * 8192, b3, n);
    k_agg<<<nb_agg, 256>>>(out, 0, n);
}

// round 10
// speedup vs baseline: 1.4085x; 1.0107x over previous
#include <cuda_runtime.h>
#include <cuda_fp16.h>
#include <cstdint>

#define D 128
#define MAXN 100096
#define EMAX 1700000
#define SPU 132

__device__ __half g_hs [MAXN * D];    // fp16: dis[i] * (x W^T + b)
__device__ __half g_buf[MAXN * D];    // fp16 layer output -> next layer input
__device__ uint2  g_wsp[3][64 * 128]; // pre-split W: {hi2, lo2} per (k2, col)
__device__ int    g_deg[MAXN];
__device__ int    g_indeg[MAXN];
__device__ int    g_off[MAXN + 1];
__device__ int    g_pos[MAXN];
__device__ int    g_csr[EMAX];
__device__ float  g_dis[MAXN];
__device__ int    g_is64;

__device__ __forceinline__ uint32_t packh2(float a, float b) {
    __half2 h = __floats2half2_rn(a, b);
    return *reinterpret_cast<uint32_t*>(&h);
}

// --------------------------------------------------------------------------
__global__ void k_pre(const int* __restrict__ e32, int n,
                      const float* __restrict__ W1,
                      const float* __restrict__ W2,
                      const float* __restrict__ W3) {
    int i = blockIdx.x * blockDim.x + threadIdx.x;
    if (i == 0) {
        int nz = 0;
        #pragma unroll 1
        for (int q = 0; q < 64; q++) nz += (e32[2 * q + 1] != 0);
        g_is64 = (nz == 0) ? 1 : 0;
    }
    if (i < n) { g_deg[i] = 1; g_indeg[i] = 0; }
    if (i < 3 * 8192) {
        const int l   = i >> 13;
        const int rem = i & 8191;
        const int k2  = rem >> 7;
        const int col = rem & 127;
        const float* W = (l == 0) ? W1 : (l == 1) ? W2 : W3;
        float w0 = W[col * 128 + 2 * k2];
        float w1 = W[col * 128 + 2 * k2 + 1];
        float h0f = __half2float(__float2half_rn(w0));
        float h1f = __half2float(__float2half_rn(w1));
        g_wsp[l][k2 * 128 + col] =
            make_uint2(packh2(w0, w1), packh2(w0 - h0f, w1 - h1f));
    }
}

__global__ void k_count(const void* __restrict__ ep, long long E) {
    long long e = (long long)blockIdx.x * blockDim.x + threadIdx.x;
    if (e >= E) return;
    int r, c;
    if (g_is64) {
        const long long* p = (const long long*)ep;
        r = (int)p[e]; c = (int)p[e + E];
    } else {
        const int* p = (const int*)ep;
        r = p[e]; c = p[e + E];
    }
    atomicAdd(&g_deg[r], 1);
    atomicAdd(&g_indeg[c], 1);
}

__global__ void k_dis(int n) {
    int i = blockIdx.x * blockDim.x + threadIdx.x;
    if (i < n) g_dis[i] = rsqrtf((float)g_deg[i]);
}

__global__ __launch_bounds__(1024) void k_scan(int n) {
    __shared__ int s[1024];
    const int t = threadIdx.x;
    const int chunk = (n + 1023) / 1024;
    const int start = t * chunk;
    const int end = min(start + chunk, n);
    int sum = 0;
    for (int i = start; i < end; i++) sum += g_indeg[i];
    s[t] = sum;
    __syncthreads();
    for (int o = 1; o < 1024; o <<= 1) {
        int v = (t >= o) ? s[t - o] : 0;
        __syncthreads();
        s[t] += v;
        __syncthreads();
    }
    int run = (t == 0) ? 0 : s[t - 1];
    for (int i = start; i < end; i++) {
        g_off[i] = run;
        g_pos[i] = run;
        run += g_indeg[i];
    }
    if (t == 1023) g_off[n] = s[1023];
}

__global__ void k_fill(const void* __restrict__ ep, long long E) {
    long long e = (long long)blockIdx.x * blockDim.x + threadIdx.x;
    if (e >= E) return;
    int r, c;
    if (g_is64) {
        const long long* p = (const long long*)ep;
        r = (int)p[e]; c = (int)p[e + E];
    } else {
        const int* p = (const int*)ep;
        r = p[e]; c = p[e + E];
    }
    int p = atomicAdd(&g_pos[c], 1);
    g_csr[p] = r;
}

// --------------------------------------------------------------------------
__device__ __forceinline__ void mma_f16(float c[4],
                                        uint32_t a0, uint32_t a1, uint32_t a2, uint32_t a3,
                                        uint32_t b0, uint32_t b1) {
    asm volatile(
        "mma.sync.aligned.m16n8k16.row.col.f32.f16.f16.f32 "
        "{%0,%1,%2,%3}, {%4,%5,%6,%7}, {%8,%9}, {%0,%1,%2,%3};"
        : "+f"(c[0]), "+f"(c[1]), "+f"(c[2]), "+f"(c[3])
        : "r"(a0), "r"(a1), "r"(a2), "r"(a3), "r"(b0), "r"(b1));
}

// layer-1 GEMM: fp32 X, hi/lo split; smem double-buffered, register prefetch
__global__ __launch_bounds__(256, 2) void k_gemm1(const float* __restrict__ X,
                                                  const uint2* __restrict__ Wsp,
                                                  const float* __restrict__ Bv,
                                                  int n) {
    __shared__ uint2 sA[2][8][SPU];
    __shared__ uint2 sB[2][8][SPU];

    const int tid  = threadIdx.x;
    const int lane = tid & 31;
    const int wid  = tid >> 5;
    const int warpRow = wid >> 1;
    const int warpCol = wid & 1;
    const int row0 = blockIdx.x * 128;
    const int lr = lane >> 2;
    const int lq = lane & 3;

    // per-thread fixed load coordinates
    const int xr0 = tid >> 2;                 // it=0: row
    const int xq0 = (tid & 3) * 4;            // it=0: k offset
    const int xr1 = (256 + tid) >> 2;
    const int xq1 = ((256 + tid) & 3) * 4;
    const int wk0 = tid >> 7, wc0 = tid & 127;

    float4 xv0, xv1;
    uint2  wv[4];

    #define G1_LOAD(K0)                                                          \
        do {                                                                     \
            int gr0 = row0 + xr0, gr1 = row0 + xr1;                              \
            xv0 = (gr0 < n) ? *(const float4*)&X[(long long)gr0 * 128 + (K0) + xq0] \
                            : make_float4(0.f, 0.f, 0.f, 0.f);                   \
            xv1 = (gr1 < n) ? *(const float4*)&X[(long long)gr1 * 128 + (K0) + xq1] \
                            : make_float4(0.f, 0.f, 0.f, 0.f);                   \
            const int k02 = (K0) >> 1;                                           \
            wv[0] = Wsp[(k02 + wk0 + 0) * 128 + wc0];                            \
            wv[1] = Wsp[(k02 + wk0 + 2) * 128 + wc0];                            \
            wv[2] = Wsp[(k02 + wk0 + 4) * 128 + wc0];                            \
            wv[3] = Wsp[(k02 + wk0 + 6) * 128 + wc0];                            \
        } while (0)

    #define G1_STORE(B)                                                          \
        do {                                                                     \
            float xe0[4] = {xv0.x, xv0.y, xv0.z, xv0.w};                         \
            float xe1[4] = {xv1.x, xv1.y, xv1.z, xv1.w};                         \
            float xl0[4], xl1[4];                                                \
            _Pragma("unroll")                                                    \
            for (int q = 0; q < 4; q++) {                                        \
                xl0[q] = xe0[q] - __half2float(__float2half_rn(xe0[q]));         \
                xl1[q] = xe1[q] - __half2float(__float2half_rn(xe1[q]));         \
            }                                                                    \
            sA[B][(xq0 >> 1) + 0][xr0] = make_uint2(packh2(xe0[0], xe0[1]), packh2(xl0[0], xl0[1])); \
            sA[B][(xq0 >> 1) + 1][xr0] = make_uint2(packh2(xe0[2], xe0[3]), packh2(xl0[2], xl0[3])); \
            sA[B][(xq1 >> 1) + 0][xr1] = make_uint2(packh2(xe1[0], xe1[1]), packh2(xl1[0], xl1[1])); \
            sA[B][(xq1 >> 1) + 1][xr1] = make_uint2(packh2(xe1[2], xe1[3]), packh2(xl1[2], xl1[3])); \
            sB[B][wk0 + 0][wc0] = wv[0];                                         \
            sB[B][wk0 + 2][wc0] = wv[1];                                         \
            sB[B][wk0 + 4][wc0] = wv[2];                                         \
            sB[B][wk0 + 6][wc0] = wv[3];                                         \
        } while (0)

    float c[2][8][4];
    #pragma unroll
    for (int mt = 0; mt < 2; mt++)
        #pragma unroll
        for (int nt = 0; nt < 8; nt++)
            #pragma unroll
            for (int q = 0; q < 4; q++) c[mt][nt][q] = 0.f;

    G1_LOAD(0);
    G1_STORE(0);
    __syncthreads();

    #pragma unroll
    for (int t = 0; t < 8; t++) {
        const int b = t & 1;
        if (t < 7) G1_LOAD((t + 1) * 16);

        uint32_t ahi[2][4], alo[2][4];
        #pragma unroll
        for (int mt = 0; mt < 2; mt++) {
            int r = warpRow * 32 + mt * 16 + lr;
            #pragma unroll
            for (int kg = 0; kg < 2; kg++) {
                uint2 v0 = sA[b][kg * 4 + lq][r];
                uint2 v1 = sA[b][kg * 4 + lq][r + 8];
                ahi[mt][kg * 2 + 0] = v0.x; alo[mt][kg * 2 + 0] = v0.y;
                ahi[mt][kg * 2 + 1] = v1.x; alo[mt][kg * 2 + 1] = v1.y;
            }
        }
        #pragma unroll
        for (int nt = 0; nt < 8; nt++) {
            int col = warpCol * 64 + nt * 8 + lr;
            uint2 w0 = sB[b][0 * 4 + lq][col];
            uint2 w1 = sB[b][1 * 4 + lq][col];
            #pragma unroll
            for (int mt = 0; mt < 2; mt++) {
                mma_f16(c[mt][nt], ahi[mt][0], ahi[mt][1], ahi[mt][2], ahi[mt][3], w0.x, w1.x);
                mma_f16(c[mt][nt], ahi[mt][0], ahi[mt][1], ahi[mt][2], ahi[mt][3], w0.y, w1.y);
                mma_f16(c[mt][nt], alo[mt][0], alo[mt][1], alo[mt][2], alo[mt][3], w0.x, w1.x);
            }
        }
        if (t < 7) G1_STORE(b ^ 1);
        __syncthreads();
    }

    #pragma unroll
    for (int mt = 0; mt < 2; mt++) {
        #pragma unroll
        for (int h2 = 0; h2 < 2; h2++) {
            int gi = row0 + warpRow * 32 + mt * 16 + lr + h2 * 8;
            if (gi >= n) continue;
            float dv = g_dis[gi];
            #pragma unroll
            for (int nt = 0; nt < 8; nt++) {
                int col = warpCol * 64 + nt * 8 + lq * 2;
                float ox = dv * (c[mt][nt][h2 * 2 + 0] + Bv[col]);
                float oy = dv * (c[mt][nt][h2 * 2 + 1] + Bv[col + 1]);
                *(__half2*)&g_hs[(long long)gi * 128 + col] = __floats2half2_rn(ox, oy);
            }
        }
    }
}

// layers 2-3 GEMM: X exact fp16; smem double-buffered, register prefetch
__global__ __launch_bounds__(256, 2) void k_gemm2(const uint2* __restrict__ Wsp,
                                                  const float* __restrict__ Bv,
                                                  int n) {
    __shared__ uint32_t sA[2][8][SPU];
    __shared__ uint2    sB[2][8][SPU];

    const int tid  = threadIdx.x;
    const int lane = tid & 31;
    const int wid  = tid >> 5;
    const int warpRow = wid >> 1;
    const int warpCol = wid & 1;
    const int row0 = blockIdx.x * 128;
    const int lr = lane >> 2;
    const int lq = lane & 3;

    const int xr0 = tid >> 2;
    const int xq0 = (tid & 3) * 4;
    const int xr1 = (256 + tid) >> 2;
    const int xq1 = ((256 + tid) & 3) * 4;
    const int wk0 = tid >> 7, wc0 = tid & 127;

    uint2 xv0, xv1;
    uint2 wv[4];

    #define G2_LOAD(K0)                                                          \
        do {                                                                     \
            int gr0 = row0 + xr0, gr1 = row0 + xr1;                              \
            xv0 = (gr0 < n) ? *(const uint2*)&g_buf[(long long)gr0 * 128 + (K0) + xq0] \
                            : make_uint2(0u, 0u);                                \
            xv1 = (gr1 < n) ? *(const uint2*)&g_buf[(long long)gr1 * 128 + (K0) + xq1] \
                            : make_uint2(0u, 0u);                                \
            const int k02 = (K0) >> 1;                                           \
            wv[0] = Wsp[(k02 + wk0 + 0) * 128 + wc0];                            \
            wv[1] = Wsp[(k02 + wk0 + 2) * 128 + wc0];                            \
            wv[2] = Wsp[(k02 + wk0 + 4) * 128 + wc0];                            \
            wv[3] = Wsp[(k02 + wk0 + 6) * 128 + wc0];                            \
        } while (0)

    #define G2_STORE(B)                                                          \
        do {                                                                     \
            sA[B][(xq0 >> 1) + 0][xr0] = xv0.x;                                  \
            sA[B][(xq0 >> 1) + 1][xr0] = xv0.y;                                  \
            sA[B][(xq1 >> 1) + 0][xr1] = xv1.x;                                  \
            sA[B][(xq1 >> 1) + 1][xr1] = xv1.y;                                  \
            sB[B][wk0 + 0][wc0] = wv[0];                                         \
            sB[B][wk0 + 2][wc0] = wv[1];                                         \
            sB[B][wk0 + 4][wc0] = wv[2];                                         \
            sB[B][wk0 + 6][wc0] = wv[3];                                         \
        } while (0)

    float c[2][8][4];
    #pragma unroll
    for (int mt = 0; mt < 2; mt++)
        #pragma unroll
        for (int nt = 0; nt < 8; nt++)
            #pragma unroll
            for (int q = 0; q < 4; q++) c[mt][nt][q] = 0.f;

    G2_LOAD(0);
    G2_STORE(0);
    __syncthreads();

    #pragma unroll
    for (int t = 0; t < 8; t++) {
        const int b = t & 1;
        if (t < 7) G2_LOAD((t + 1) * 16);

        uint32_t a[2][4];
        #pragma unroll
        for (int mt = 0; mt < 2; mt++) {
            int r = warpRow * 32 + mt * 16 + lr;
            #pragma unroll
            for (int kg = 0; kg < 2; kg++) {
                a[mt][kg * 2 + 0] = sA[b][kg * 4 + lq][r];
                a[mt][kg * 2 + 1] = sA[b][kg * 4 + lq][r + 8];
            }
        }
        #pragma unroll
        for (int nt = 0; nt < 8; nt++) {
            int col = warpCol * 64 + nt * 8 + lr;
            uint2 w0 = sB[b][0 * 4 + lq][col];
            uint2 w1 = sB[b][1 * 4 + lq][col];
            #pragma unroll
            for (int mt = 0; mt < 2; mt++) {
                mma_f16(c[mt][nt], a[mt][0], a[mt][1], a[mt][2], a[mt][3], w0.x, w1.x);
                mma_f16(c[mt][nt], a[mt][0], a[mt][1], a[mt][2], a[mt][3], w0.y, w1.y);
            }
        }
        if (t < 7) G2_STORE(b ^ 1);
        __syncthreads();
    }

    #pragma unroll
    for (int mt = 0; mt < 2; mt++) {
        #pragma unroll
        for (int h2 = 0; h2 < 2; h2++) {
            int gi = row0 + warpRow * 32 + mt * 16 + lr + h2 * 8;
            if (gi >= n) continue;
            float dv = g_dis[gi];
            #pragma unroll
            for (int nt = 0; nt < 8; nt++) {
                int col = warpCol * 64 + nt * 8 + lq * 2;
                float ox = dv * (c[mt][nt][h2 * 2 + 0] + Bv[col]);
                float oy = dv * (c[mt][nt][h2 * 2 + 1] + Bv[col + 1]);
                *(__half2*)&g_hs[(long long)gi * 128 + col] = __floats2half2_rn(ox, oy);
            }
        }
    }
}

// --------------------------------------------------------------------------
// Pull aggregation v4 (unchanged from R9 winner)
// --------------------------------------------------------------------------
#define ACC8(v)                                                                 \
    do {                                                                        \
        float2 f;                                                               \
        f = __half22float2(*reinterpret_cast<__half2*>(&(v).x)); a0 += f.x; a1 += f.y; \
        f = __half22float2(*reinterpret_cast<__half2*>(&(v).y)); a2 += f.x; a3 += f.y; \
        f = __half22float2(*reinterpret_cast<__half2*>(&(v).z)); a4 += f.x; a5 += f.y; \
        f = __half22float2(*reinterpret_cast<__half2*>(&(v).w)); a6 += f.x; a7 += f.y; \
    } while (0)

__global__ __launch_bounds__(256) void k_agg(float* __restrict__ dst,
                                             int to_buf, int n) {
    const int node = blockIdx.x * 8 + (threadIdx.x >> 5);
    if (node >= n) return;
    const int lane = threadIdx.x & 31;
    const int hl = lane >> 4;
    const int sl = lane & 15;

    const int beg = g_off[node];
    const int end = g_off[node + 1];

    const uint4* hsb = (const uint4*)g_hs;

    float a0 = 0.f, a1 = 0.f, a2 = 0.f, a3 = 0.f,
          a4 = 0.f, a5 = 0.f, a6 = 0.f, a7 = 0.f;

    if (hl == 0) {
        uint4 v = hsb[(long long)node * 16 + sl];
        ACC8(v);
    }

    int j = beg + hl;
    for (; j + 14 < end; j += 16) {
        int i0 = __ldg(&g_csr[j + 0]);
        int i1 = __ldg(&g_csr[j + 2]);
        int i2 = __ldg(&g_csr[j + 4]);
        int i3 = __ldg(&g_csr[j + 6]);
        int i4 = __ldg(&g_csr[j + 8]);
        int i5 = __ldg(&g_csr[j + 10]);
        int i6 = __ldg(&g_csr[j + 12]);
        int i7 = __ldg(&g_csr[j + 14]);
        uint4 v0 = __ldg(&hsb[(long long)i0 * 16 + sl]);
        uint4 v1 = __ldg(&hsb[(long long)i1 * 16 + sl]);
        uint4 v2 = __ldg(&hsb[(long long)i2 * 16 + sl]);
        uint4 v3 = __ldg(&hsb[(long long)i3 * 16 + sl]);
        uint4 v4 = __ldg(&hsb[(long long)i4 * 16 + sl]);
        uint4 v5 = __ldg(&hsb[(long long)i5 * 16 + sl]);
        uint4 v6 = __ldg(&hsb[(long long)i6 * 16 + sl]);
        uint4 v7 = __ldg(&hsb[(long long)i7 * 16 + sl]);
        ACC8(v0); ACC8(v1); ACC8(v2); ACC8(v3);
        ACC8(v4); ACC8(v5); ACC8(v6); ACC8(v7);
    }
    for (; j < end; j += 2) {
        int i0 = __ldg(&g_csr[j]);
        uint4 v0 = __ldg(&hsb[(long long)i0 * 16 + sl]);
        ACC8(v0);
    }

    a0 += __shfl_xor_sync(0xffffffffu, a0, 16);
    a1 += __shfl_xor_sync(0xffffffffu, a1, 16);
    a2 += __shfl_xor_sync(0xffffffffu, a2, 16);
    a3 += __shfl_xor_sync(0xffffffffu, a3, 16);
    a4 += __shfl_xor_sync(0xffffffffu, a4, 16);
    a5 += __shfl_xor_sync(0xffffffffu, a5, 16);
    a6 += __shfl_xor_sync(0xffffffffu, a6, 16);
    a7 += __shfl_xor_sync(0xffffffffu, a7, 16);

    const float dv = g_dis[node];
    a0 = fmaxf(dv * a0, 0.f); a1 = fmaxf(dv * a1, 0.f);
    a2 = fmaxf(dv * a2, 0.f); a3 = fmaxf(dv * a3, 0.f);
    a4 = fmaxf(dv * a4, 0.f); a5 = fmaxf(dv * a5, 0.f);
    a6 = fmaxf(dv * a6, 0.f); a7 = fmaxf(dv * a7, 0.f);

    if (hl == 0) {
        if (to_buf) {
            uint4 o;
            o.x = packh2(a0, a1); o.y = packh2(a2, a3);
            o.z = packh2(a4, a5); o.w = packh2(a6, a7);
            ((uint4*)g_buf)[(long long)node * 16 + sl] = o;
        } else {
            float4* op = (float4*)&dst[((long long)node << 7) + sl * 8];
            op[0] = make_float4(a0, a1, a2, a3);
            op[1] = make_float4(a4, a5, a6, a7);
        }
    }
}

// --------------------------------------------------------------------------
extern "C" void kernel_launch(void* const* d_in, const int* in_sizes, int n_in,
                              void* d_out, int out_size) {
    const float* x  = (const float*)d_in[0];
    const void*  ep = d_in[1];
    const float* W1 = (const float*)d_in[2];
    const float* b1 = (const float*)d_in[3];
    const float* W2 = (const float*)d_in[4];
    const float* b2 = (const float*)d_in[5];
    const float* W3 = (const float*)d_in[6];
    const float* b3 = (const float*)d_in[7];
    float* out = (float*)d_out;

    const int n = in_sizes[0] / D;
    const long long E = (long long)in_sizes[1] / 2;

    const int tb = 256;
    const int nb_n    = (n + tb - 1) / tb;
    const int nb_e    = (int)((E + tb - 1) / tb);
    const int nb_gemm = (n + 127) / 128;
    const int nb_agg  = (n + 7) / 8;

    uint2* wsp;
    cudaGetSymbolAddress((void**)&wsp, g_wsp);

    static cudaStream_t s2 = nullptr;
    static cudaEvent_t ev1 = nullptr, ev2 = nullptr;
    if (s2 == nullptr) {
        cudaStreamCreateWithFlags(&s2, cudaStreamNonBlocking);
        cudaEventCreateWithFlags(&ev1, cudaEventDisableTiming);
        cudaEventCreateWithFlags(&ev2, cudaEventDisableTiming);
    }

    k_pre<<<nb_n, tb>>>((const int*)ep, n, W1, W2, W3);
    k_count<<<nb_e, tb>>>(ep, E);
    cudaEventRecord(ev1, 0);

    cudaStreamWaitEvent(s2, ev1, 0);
    k_scan<<<1, 1024, 0, s2>>>(n);
    k_fill<<<nb_e, tb, 0, s2>>>(ep, E);
    cudaEventRecord(ev2, s2);

    k_dis<<<nb_n, tb>>>(n);
    k_gemm1<<<nb_gemm, 256>>>(x, wsp, b1, n);

    cudaStreamWaitEvent(0, ev2, 0);
    k_agg<<<nb_agg, 256>>>(out, 1, n);
    k_gemm2<<<nb_gemm, 256>>>(wsp + 8192, b2, n);
    k_agg<<<nb_agg, 256>>>(out, 1, n);
    k_gemm2<<<nb_gemm, 256>>>(wsp + 2 * 8192, b3, n);
    k_agg<<<nb_agg, 256>>>(out, 0, n);
}

// round 11
// speedup vs baseline: 1.4787x; 1.0498x over previous
#include <cuda_runtime.h>
#include <cuda_fp16.h>
#include <cstdint>

#define D 128
#define MAXN 100096
#define EMAX 1700000
#define SPU 132

__device__ __half g_hs [MAXN * D];    // fp16: dis[i] * (x W^T + b)
__device__ __half g_buf[MAXN * D];    // fp16 layer output -> next layer input
__device__ uint2  g_wsp[3][64 * 128]; // pre-split W: {hi2, lo2} per (k2, col)
__device__ int    g_deg[MAXN];
__device__ int    g_indeg[MAXN];
__device__ int    g_off[MAXN + 1];
__device__ int    g_pos[MAXN];
__device__ int    g_csr[EMAX];
__device__ float  g_dis[MAXN];
__device__ int    g_is64;

__device__ __forceinline__ uint32_t packh2(float a, float b) {
    __half2 h = __floats2half2_rn(a, b);
    return *reinterpret_cast<uint32_t*>(&h);
}

// --------------------------------------------------------------------------
__global__ void k_pre(const int* __restrict__ e32, int n,
                      const float* __restrict__ W1,
                      const float* __restrict__ W2,
                      const float* __restrict__ W3) {
    int i = blockIdx.x * blockDim.x + threadIdx.x;
    if (i == 0) {
        int nz = 0;
        #pragma unroll 1
        for (int q = 0; q < 64; q++) nz += (e32[2 * q + 1] != 0);
        g_is64 = (nz == 0) ? 1 : 0;
    }
    if (i < n) { g_deg[i] = 1; g_indeg[i] = 0; }
    if (i < 3 * 8192) {
        const int l   = i >> 13;
        const int rem = i & 8191;
        const int k2  = rem >> 7;
        const int col = rem & 127;
        const float* W = (l == 0) ? W1 : (l == 1) ? W2 : W3;
        float w0 = W[col * 128 + 2 * k2];
        float w1 = W[col * 128 + 2 * k2 + 1];
        float h0f = __half2float(__float2half_rn(w0));
        float h1f = __half2float(__float2half_rn(w1));
        g_wsp[l][k2 * 128 + col] =
            make_uint2(packh2(w0, w1), packh2(w0 - h0f, w1 - h1f));
    }
}

__global__ void k_count(const void* __restrict__ ep, long long E) {
    long long e = (long long)blockIdx.x * blockDim.x + threadIdx.x;
    if (e >= E) return;
    int r, c;
    if (g_is64) {
        const long long* p = (const long long*)ep;
        r = (int)p[e]; c = (int)p[e + E];
    } else {
        const int* p = (const int*)ep;
        r = p[e]; c = p[e + E];
    }
    atomicAdd(&g_deg[r], 1);
    atomicAdd(&g_indeg[c], 1);
}

__global__ void k_dis(int n) {
    int i = blockIdx.x * blockDim.x + threadIdx.x;
    if (i < n) g_dis[i] = rsqrtf((float)g_deg[i]);
}

__global__ __launch_bounds__(1024) void k_scan(int n) {
    __shared__ int s[1024];
    const int t = threadIdx.x;
    const int chunk = (n + 1023) / 1024;
    const int start = t * chunk;
    const int end = min(start + chunk, n);
    int sum = 0;
    for (int i = start; i < end; i++) sum += g_indeg[i];
    s[t] = sum;
    __syncthreads();
    for (int o = 1; o < 1024; o <<= 1) {
        int v = (t >= o) ? s[t - o] : 0;
        __syncthreads();
        s[t] += v;
        __syncthreads();
    }
    int run = (t == 0) ? 0 : s[t - 1];
    for (int i = start; i < end; i++) {
        g_off[i] = run;
        g_pos[i] = run;
        run += g_indeg[i];
    }
    if (t == 1023) g_off[n] = s[1023];
}

__global__ void k_fill(const void* __restrict__ ep, long long E) {
    long long e = (long long)blockIdx.x * blockDim.x + threadIdx.x;
    if (e >= E) return;
    int r, c;
    if (g_is64) {
        const long long* p = (const long long*)ep;
        r = (int)p[e]; c = (int)p[e + E];
    } else {
        const int* p = (const int*)ep;
        r = p[e]; c = p[e + E];
    }
    int p = atomicAdd(&g_pos[c], 1);
    g_csr[p] = r;
}

// --------------------------------------------------------------------------
__device__ __forceinline__ void mma_f16(float c[4],
                                        uint32_t a0, uint32_t a1, uint32_t a2, uint32_t a3,
                                        uint32_t b0, uint32_t b1) {
    asm volatile(
        "mma.sync.aligned.m16n8k16.row.col.f32.f16.f16.f32 "
        "{%0,%1,%2,%3}, {%4,%5,%6,%7}, {%8,%9}, {%0,%1,%2,%3};"
        : "+f"(c[0]), "+f"(c[1]), "+f"(c[2]), "+f"(c[3])
        : "r"(a0), "r"(a1), "r"(a2), "r"(a3), "r"(b0), "r"(b1));
}

// layer-1 GEMM: fp32 X, hi/lo split; smem double-buffered, register prefetch
__global__ __launch_bounds__(256, 2) void k_gemm1(const float* __restrict__ X,
                                                  const uint2* __restrict__ Wsp,
                                                  const float* __restrict__ Bv,
                                                  int n) {
    __shared__ uint2 sA[2][8][SPU];
    __shared__ uint2 sB[2][8][SPU];

    const int tid  = threadIdx.x;
    const int lane = tid & 31;
    const int wid  = tid >> 5;
    const int warpRow = wid >> 1;
    const int warpCol = wid & 1;
    const int row0 = blockIdx.x * 128;
    const int lr = lane >> 2;
    const int lq = lane & 3;

    const int xr0 = tid >> 2;
    const int xq0 = (tid & 3) * 4;
    const int xr1 = (256 + tid) >> 2;
    const int xq1 = ((256 + tid) & 3) * 4;
    const int wk0 = tid >> 7, wc0 = tid & 127;

    float4 xv0, xv1;
    uint2  wv[4];

    #define G1_LOAD(K0)                                                          \
        do {                                                                     \
            int gr0 = row0 + xr0, gr1 = row0 + xr1;                              \
            xv0 = (gr0 < n) ? *(const float4*)&X[(long long)gr0 * 128 + (K0) + xq0] \
                            : make_float4(0.f, 0.f, 0.f, 0.f);                   \
            xv1 = (gr1 < n) ? *(const float4*)&X[(long long)gr1 * 128 + (K0) + xq1] \
                            : make_float4(0.f, 0.f, 0.f, 0.f);                   \
            const int k02 = (K0) >> 1;                                           \
            wv[0] = Wsp[(k02 + wk0 + 0) * 128 + wc0];                            \
            wv[1] = Wsp[(k02 + wk0 + 2) * 128 + wc0];                            \
            wv[2] = Wsp[(k02 + wk0 + 4) * 128 + wc0];                            \
            wv[3] = Wsp[(k02 + wk0 + 6) * 128 + wc0];                            \
        } while (0)

    #define G1_STORE(B)                                                          \
        do {                                                                     \
            float xe0[4] = {xv0.x, xv0.y, xv0.z, xv0.w};                         \
            float xe1[4] = {xv1.x, xv1.y, xv1.z, xv1.w};                         \
            float xl0[4], xl1[4];                                                \
            _Pragma("unroll")                                                    \
            for (int q = 0; q < 4; q++) {                                        \
                xl0[q] = xe0[q] - __half2float(__float2half_rn(xe0[q]));         \
                xl1[q] = xe1[q] - __half2float(__float2half_rn(xe1[q]));         \
            }                                                                    \
            sA[B][(xq0 >> 1) + 0][xr0] = make_uint2(packh2(xe0[0], xe0[1]), packh2(xl0[0], xl0[1])); \
            sA[B][(xq0 >> 1) + 1][xr0] = make_uint2(packh2(xe0[2], xe0[3]), packh2(xl0[2], xl0[3])); \
            sA[B][(xq1 >> 1) + 0][xr1] = make_uint2(packh2(xe1[0], xe1[1]), packh2(xl1[0], xl1[1])); \
            sA[B][(xq1 >> 1) + 1][xr1] = make_uint2(packh2(xe1[2], xe1[3]), packh2(xl1[2], xl1[3])); \
            sB[B][wk0 + 0][wc0] = wv[0];                                         \
            sB[B][wk0 + 2][wc0] = wv[1];                                         \
            sB[B][wk0 + 4][wc0] = wv[2];                                         \
            sB[B][wk0 + 6][wc0] = wv[3];                                         \
        } while (0)

    float c[2][8][4];
    #pragma unroll
    for (int mt = 0; mt < 2; mt++)
        #pragma unroll
        for (int nt = 0; nt < 8; nt++)
            #pragma unroll
            for (int q = 0; q < 4; q++) c[mt][nt][q] = 0.f;

    G1_LOAD(0);
    G1_STORE(0);
    __syncthreads();

    #pragma unroll
    for (int t = 0; t < 8; t++) {
        const int b = t & 1;
        if (t < 7) G1_LOAD((t + 1) * 16);

        uint32_t ahi[2][4], alo[2][4];
        #pragma unroll
        for (int mt = 0; mt < 2; mt++) {
            int r = warpRow * 32 + mt * 16 + lr;
            #pragma unroll
            for (int kg = 0; kg < 2; kg++) {
                uint2 v0 = sA[b][kg * 4 + lq][r];
                uint2 v1 = sA[b][kg * 4 + lq][r + 8];
                ahi[mt][kg * 2 + 0] = v0.x; alo[mt][kg * 2 + 0] = v0.y;
                ahi[mt][kg * 2 + 1] = v1.x; alo[mt][kg * 2 + 1] = v1.y;
            }
        }
        #pragma unroll
        for (int nt = 0; nt < 8; nt++) {
            int col = warpCol * 64 + nt * 8 + lr;
            uint2 w0 = sB[b][0 * 4 + lq][col];
            uint2 w1 = sB[b][1 * 4 + lq][col];
            #pragma unroll
            for (int mt = 0; mt < 2; mt++) {
                mma_f16(c[mt][nt], ahi[mt][0], ahi[mt][1], ahi[mt][2], ahi[mt][3], w0.x, w1.x);
                mma_f16(c[mt][nt], ahi[mt][0], ahi[mt][1], ahi[mt][2], ahi[mt][3], w0.y, w1.y);
                mma_f16(c[mt][nt], alo[mt][0], alo[mt][1], alo[mt][2], alo[mt][3], w0.x, w1.x);
            }
        }
        if (t < 7) G1_STORE(b ^ 1);
        __syncthreads();
    }

    #pragma unroll
    for (int mt = 0; mt < 2; mt++) {
        #pragma unroll
        for (int h2 = 0; h2 < 2; h2++) {
            int gi = row0 + warpRow * 32 + mt * 16 + lr + h2 * 8;
            if (gi >= n) continue;
            float dv = g_dis[gi];
            #pragma unroll
            for (int nt = 0; nt < 8; nt++) {
                int col = warpCol * 64 + nt * 8 + lq * 2;
                float ox = dv * (c[mt][nt][h2 * 2 + 0] + Bv[col]);
                float oy = dv * (c[mt][nt][h2 * 2 + 1] + Bv[col + 1]);
                *(__half2*)&g_hs[(long long)gi * 128 + col] = __floats2half2_rn(ox, oy);
            }
        }
    }
}

// layers 2-3 GEMM: X exact fp16; smem double-buffered, register prefetch
__global__ __launch_bounds__(256, 2) void k_gemm2(const uint2* __restrict__ Wsp,
                                                  const float* __restrict__ Bv,
                                                  int n) {
    __shared__ uint32_t sA[2][8][SPU];
    __shared__ uint2    sB[2][8][SPU];

    const int tid  = threadIdx.x;
    const int lane = tid & 31;
    const int wid  = tid >> 5;
    const int warpRow = wid >> 1;
    const int warpCol = wid & 1;
    const int row0 = blockIdx.x * 128;
    const int lr = lane >> 2;
    const int lq = lane & 3;

    const int xr0 = tid >> 2;
    const int xq0 = (tid & 3) * 4;
    const int xr1 = (256 + tid) >> 2;
    const int xq1 = ((256 + tid) & 3) * 4;
    const int wk0 = tid >> 7, wc0 = tid & 127;

    uint2 xv0, xv1;
    uint2 wv[4];

    #define G2_LOAD(K0)                                                          \
        do {                                                                     \
            int gr0 = row0 + xr0, gr1 = row0 + xr1;                              \
            xv0 = (gr0 < n) ? *(const uint2*)&g_buf[(long long)gr0 * 128 + (K0) + xq0] \
                            : make_uint2(0u, 0u);                                \
            xv1 = (gr1 < n) ? *(const uint2*)&g_buf[(long long)gr1 * 128 + (K0) + xq1] \
                            : make_uint2(0u, 0u);                                \
            const int k02 = (K0) >> 1;                                           \
            wv[0] = Wsp[(k02 + wk0 + 0) * 128 + wc0];                            \
            wv[1] = Wsp[(k02 + wk0 + 2) * 128 + wc0];                            \
            wv[2] = Wsp[(k02 + wk0 + 4) * 128 + wc0];                            \
            wv[3] = Wsp[(k02 + wk0 + 6) * 128 + wc0];                            \
        } while (0)

    #define G2_STORE(B)                                                          \
        do {                                                                     \
            sA[B][(xq0 >> 1) + 0][xr0] = xv0.x;                                  \
            sA[B][(xq0 >> 1) + 1][xr0] = xv0.y;                                  \
            sA[B][(xq1 >> 1) + 0][xr1] = xv1.x;                                  \
            sA[B][(xq1 >> 1) + 1][xr1] = xv1.y;                                  \
            sB[B][wk0 + 0][wc0] = wv[0];                                         \
            sB[B][wk0 + 2][wc0] = wv[1];                                         \
            sB[B][wk0 + 4][wc0] = wv[2];                                         \
            sB[B][wk0 + 6][wc0] = wv[3];                                         \
        } while (0)

    float c[2][8][4];
    #pragma unroll
    for (int mt = 0; mt < 2; mt++)
        #pragma unroll
        for (int nt = 0; nt < 8; nt++)
            #pragma unroll
            for (int q = 0; q < 4; q++) c[mt][nt][q] = 0.f;

    G2_LOAD(0);
    G2_STORE(0);
    __syncthreads();

    #pragma unroll
    for (int t = 0; t < 8; t++) {
        const int b = t & 1;
        if (t < 7) G2_LOAD((t + 1) * 16);

        uint32_t a[2][4];
        #pragma unroll
        for (int mt = 0; mt < 2; mt++) {
            int r = warpRow * 32 + mt * 16 + lr;
            #pragma unroll
            for (int kg = 0; kg < 2; kg++) {
                a[mt][kg * 2 + 0] = sA[b][kg * 4 + lq][r];
                a[mt][kg * 2 + 1] = sA[b][kg * 4 + lq][r + 8];
            }
        }
        #pragma unroll
        for (int nt = 0; nt < 8; nt++) {
            int col = warpCol * 64 + nt * 8 + lr;
            uint2 w0 = sB[b][0 * 4 + lq][col];
            uint2 w1 = sB[b][1 * 4 + lq][col];
            #pragma unroll
            for (int mt = 0; mt < 2; mt++) {
                mma_f16(c[mt][nt], a[mt][0], a[mt][1], a[mt][2], a[mt][3], w0.x, w1.x);
                mma_f16(c[mt][nt], a[mt][0], a[mt][1], a[mt][2], a[mt][3], w0.y, w1.y);
            }
        }
        if (t < 7) G2_STORE(b ^ 1);
        __syncthreads();
    }

    #pragma unroll
    for (int mt = 0; mt < 2; mt++) {
        #pragma unroll
        for (int h2 = 0; h2 < 2; h2++) {
            int gi = row0 + warpRow * 32 + mt * 16 + lr + h2 * 8;
            if (gi >= n) continue;
            float dv = g_dis[gi];
            #pragma unroll
            for (int nt = 0; nt < 8; nt++) {
                int col = warpCol * 64 + nt * 8 + lq * 2;
                float ox = dv * (c[mt][nt][h2 * 2 + 0] + Bv[col]);
                float oy = dv * (c[mt][nt][h2 * 2 + 1] + Bv[col + 1]);
                *(__half2*)&g_hs[(long long)gi * 128 + col] = __floats2half2_rn(ox, oy);
            }
        }
    }
}

// --------------------------------------------------------------------------
// Pull aggregation v5: one node per HALF-warp (16 lanes x uint4 = 256B row).
// 8-row batches combined with a depth-2 fp16 HADD2 tree, then fp32 accumulate.
// --------------------------------------------------------------------------
__device__ __forceinline__ uint32_t hadd2u(uint32_t a, uint32_t b) {
    __half2 r = __hadd2(*reinterpret_cast<__half2*>(&a),
                        *reinterpret_cast<__half2*>(&b));
    return *reinterpret_cast<uint32_t*>(&r);
}

#define ACCF(u)                                                                  \
    do {                                                                         \
        uint32_t _t = (u);                                                       \
        float2 _f = __half22float2(*reinterpret_cast<__half2*>(&_t));            \
        /* consumer sets targets via macro args below */                          \
    } while (0)

__global__ __launch_bounds__(256) void k_agg(float* __restrict__ dst,
                                             int to_buf, int n) {
    const int node = (blockIdx.x * 256 + threadIdx.x) >> 4;   // half-warp id
    if (node >= n) return;
    const int sl = threadIdx.x & 15;

    const int beg = g_off[node];
    const int end = g_off[node + 1];

    const uint4* hsb = (const uint4*)g_hs;

    float a0, a1, a2, a3, a4, a5, a6, a7;
    {   // self-loop row
        uint4 v = hsb[(long long)node * 16 + sl];
        float2 f;
        f = __half22float2(*reinterpret_cast<__half2*>(&v.x)); a0 = f.x; a1 = f.y;
        f = __half22float2(*reinterpret_cast<__half2*>(&v.y)); a2 = f.x; a3 = f.y;
        f = __half22float2(*reinterpret_cast<__half2*>(&v.z)); a4 = f.x; a5 = f.y;
        f = __half22float2(*reinterpret_cast<__half2*>(&v.w)); a6 = f.x; a7 = f.y;
    }

    int j = beg;
    for (; j + 8 <= end; j += 8) {
        int i0 = __ldg(&g_csr[j + 0]);
        int i1 = __ldg(&g_csr[j + 1]);
        int i2 = __ldg(&g_csr[j + 2]);
        int i3 = __ldg(&g_csr[j + 3]);
        int i4 = __ldg(&g_csr[j + 4]);
        int i5 = __ldg(&g_csr[j + 5]);
        int i6 = __ldg(&g_csr[j + 6]);
        int i7 = __ldg(&g_csr[j + 7]);
        uint4 v0 = __ldg(&hsb[(long long)i0 * 16 + sl]);
        uint4 v1 = __ldg(&hsb[(long long)i1 * 16 + sl]);
        uint4 v2 = __ldg(&hsb[(long long)i2 * 16 + sl]);
        uint4 v3 = __ldg(&hsb[(long long)i3 * 16 + sl]);
        uint4 v4 = __ldg(&hsb[(long long)i4 * 16 + sl]);
        uint4 v5 = __ldg(&hsb[(long long)i5 * 16 + sl]);
        uint4 v6 = __ldg(&hsb[(long long)i6 * 16 + sl]);
        uint4 v7 = __ldg(&hsb[(long long)i7 * 16 + sl]);
        // depth-2 fp16 tree: (v0+v1)+(v2+v3), (v4+v5)+(v6+v7)
        uint4 sA4, sB4;
        sA4.x = hadd2u(hadd2u(v0.x, v1.x), hadd2u(v2.x, v3.x));
        sA4.y = hadd2u(hadd2u(v0.y, v1.y), hadd2u(v2.y, v3.y));
        sA4.z = hadd2u(hadd2u(v0.z, v1.z), hadd2u(v2.z, v3.z));
        sA4.w = hadd2u(hadd2u(v0.w, v1.w), hadd2u(v2.w, v3.w));
        sB4.x = hadd2u(hadd2u(v4.x, v5.x), hadd2u(v6.x, v7.x));
        sB4.y = hadd2u(hadd2u(v4.y, v5.y), hadd2u(v6.y, v7.y));
        sB4.z = hadd2u(hadd2u(v4.z, v5.z), hadd2u(v6.z, v7.z));
        sB4.w = hadd2u(hadd2u(v4.w, v5.w), hadd2u(v6.w, v7.w));
        float2 f;
        f = __half22float2(*reinterpret_cast<__half2*>(&sA4.x)); a0 += f.x; a1 += f.y;
        f = __half22float2(*reinterpret_cast<__half2*>(&sA4.y)); a2 += f.x; a3 += f.y;
        f = __half22float2(*reinterpret_cast<__half2*>(&sA4.z)); a4 += f.x; a5 += f.y;
        f = __half22float2(*reinterpret_cast<__half2*>(&sA4.w)); a6 += f.x; a7 += f.y;
        f = __half22float2(*reinterpret_cast<__half2*>(&sB4.x)); a0 += f.x; a1 += f.y;
        f = __half22float2(*reinterpret_cast<__half2*>(&sB4.y)); a2 += f.x; a3 += f.y;
        f = __half22float2(*reinterpret_cast<__half2*>(&sB4.z)); a4 += f.x; a5 += f.y;
        f = __half22float2(*reinterpret_cast<__half2*>(&sB4.w)); a6 += f.x; a7 += f.y;
    }
    for (; j < end; j++) {
        int i0 = __ldg(&g_csr[j]);
        uint4 v0 = __ldg(&hsb[(long long)i0 * 16 + sl]);
        float2 f;
        f = __half22float2(*reinterpret_cast<__half2*>(&v0.x)); a0 += f.x; a1 += f.y;
        f = __half22float2(*reinterpret_cast<__half2*>(&v0.y)); a2 += f.x; a3 += f.y;
        f = __half22float2(*reinterpret_cast<__half2*>(&v0.z)); a4 += f.x; a5 += f.y;
        f = __half22float2(*reinterpret_cast<__half2*>(&v0.w)); a6 += f.x; a7 += f.y;
    }

    const float dv = g_dis[node];
    a0 = fmaxf(dv * a0, 0.f); a1 = fmaxf(dv * a1, 0.f);
    a2 = fmaxf(dv * a2, 0.f); a3 = fmaxf(dv * a3, 0.f);
    a4 = fmaxf(dv * a4, 0.f); a5 = fmaxf(dv * a5, 0.f);
    a6 = fmaxf(dv * a6, 0.f); a7 = fmaxf(dv * a7, 0.f);

    if (to_buf) {
        uint4 o;
        o.x = packh2(a0, a1); o.y = packh2(a2, a3);
        o.z = packh2(a4, a5); o.w = packh2(a6, a7);
        ((uint4*)g_buf)[(long long)node * 16 + sl] = o;
    } else {
        float4* op = (float4*)&dst[((long long)node << 7) + sl * 8];
        op[0] = make_float4(a0, a1, a2, a3);
        op[1] = make_float4(a4, a5, a6, a7);
    }
}

// --------------------------------------------------------------------------
extern "C" void kernel_launch(void* const* d_in, const int* in_sizes, int n_in,
                              void* d_out, int out_size) {
    const float* x  = (const float*)d_in[0];
    const void*  ep = d_in[1];
    const float* W1 = (const float*)d_in[2];
    const float* b1 = (const float*)d_in[3];
    const float* W2 = (const float*)d_in[4];
    const float* b2 = (const float*)d_in[5];
    const float* W3 = (const float*)d_in[6];
    const float* b3 = (const float*)d_in[7];
    float* out = (float*)d_out;

    const int n = in_sizes[0] / D;
    const long long E = (long long)in_sizes[1] / 2;

    const int tb = 256;
    const int nb_n    = (n + tb - 1) / tb;
    const int nb_e    = (int)((E + tb - 1) / tb);
    const int nb_gemm = (n + 127) / 128;
    const int nb_agg  = (n + 15) / 16;

    uint2* wsp;
    cudaGetSymbolAddress((void**)&wsp, g_wsp);

    static cudaStream_t s2 = nullptr;
    static cudaEvent_t ev1 = nullptr, ev2 = nullptr;
    if (s2 == nullptr) {
        cudaStreamCreateWithFlags(&s2, cudaStreamNonBlocking);
        cudaEventCreateWithFlags(&ev1, cudaEventDisableTiming);
        cudaEventCreateWithFlags(&ev2, cudaEventDisableTiming);
    }

    k_pre<<<nb_n, tb>>>((const int*)ep, n, W1, W2, W3);
    k_count<<<nb_e, tb>>>(ep, E);
    cudaEventRecord(ev1, 0);

    cudaStreamWaitEvent(s2, ev1, 0);
    k_scan<<<1, 1024, 0, s2>>>(n);
    k_fill<<<nb_e, tb, 0, s2>>>(ep, E);
    cudaEventRecord(ev2, s2);

    k_dis<<<nb_n, tb>>>(n);
    k_gemm1<<<nb_gemm, 256>>>(x, wsp, b1, n);

    cudaStreamWaitEvent(0, ev2, 0);
    k_agg<<<nb_agg, 256>>>(out, 1, n);
    k_gemm2<<<nb_gemm, 256>>>(wsp + 8192, b2, n);
    k_agg<<<nb_agg, 256>>>(out, 1, n);
    k_gemm2<<<nb_gemm, 256>>>(wsp + 2 * 8192, b3, n);
    k_agg<<<nb_agg, 256>>>(out, 0, n);
}